// round 14
// baseline (speedup 1.0000x reference)
#include <cuda_runtime.h>
#include <cstdint>
#include <math.h>

#define N_TOK 10368          // 2*72*72
#define HS    1024
#define NWH   288            // 18 windows * 16 heads
#define S_WIN 576            // 24*24
#define HD    64

// ---------------- scratch (static device arrays; no runtime allocation) ----
__device__ float g_xn[N_TOK * HS];              // LN1 out; later split-K partial 0
__device__ float g_qw[NWH * S_WIN * HD];
__device__ float g_kw[NWH * S_WIN * HD];
__device__ float g_vwT[NWH * HD * S_WIN];       // [wh][d][s]
__device__ float g_of[N_TOK * HS];              // attn out; later split-K partial 1
__device__ float g_yn[N_TOK * HS];
__device__ float g_hm[(size_t)N_TOK * 4096];
// transposed (k-major) tf32-rounded weights
__device__ float g_wqkvT[3 * HS * HS];          // [3072][1024]
__device__ float g_bqkv[3 * HS];
__device__ float g_woT[HS * HS];
__device__ float g_w1T[HS * 4096];
__device__ float g_w2T[HS * 4096];

// ============================ helpers =======================================
__device__ __forceinline__ uint32_t smem_u32(const void* p) {
    uint32_t a;
    asm("{ .reg .u64 t; cvta.to.shared.u64 t, %1; cvt.u32.u64 %0, t; }"
        : "=r"(a) : "l"(p));
    return a;
}

__device__ __forceinline__ float rndf(float x) {   // round fp32 -> tf32-representable
    uint32_t r;
    asm("cvt.rna.tf32.f32 %0, %1;" : "=r"(r) : "f"(x));
    return __uint_as_float(r);
}

__device__ __forceinline__ void cp16(uint32_t dst, const void* src) {
    asm volatile("cp.async.cg.shared.global [%0], [%1], 16;"
                 :: "r"(dst), "l"(src) : "memory");
}
__device__ __forceinline__ void cp_commit() {
    asm volatile("cp.async.commit_group;" ::: "memory");
}
template <int N>
__device__ __forceinline__ void cp_wait() {
    asm volatile("cp.async.wait_group %0;" :: "n"(N) : "memory");
}

__device__ __forceinline__ void mma16n8k8(float* c, uint32_t a0, uint32_t a1,
                                          uint32_t a2, uint32_t a3,
                                          uint32_t b0, uint32_t b1) {
    asm volatile(
        "mma.sync.aligned.m16n8k8.row.col.f32.tf32.tf32.f32 "
        "{%0,%1,%2,%3}, {%4,%5,%6,%7}, {%8,%9}, {%0,%1,%2,%3};"
        : "+f"(c[0]), "+f"(c[1]), "+f"(c[2]), "+f"(c[3])
        : "r"(a0), "r"(a1), "r"(a2), "r"(a3), "r"(b0), "r"(b1));
}

__device__ __forceinline__ void ldsm4(uint32_t& r0, uint32_t& r1, uint32_t& r2,
                                      uint32_t& r3, uint32_t addr) {
    asm volatile("ldmatrix.sync.aligned.m8n8.x4.shared.b16 {%0,%1,%2,%3}, [%4];"
                 : "=r"(r0), "=r"(r1), "=r"(r2), "=r"(r3) : "r"(addr));
}

// ============================ tf32 mma.sync GEMM ============================
// C[M,N] = A[M,K] @ Bt[n][k]^T + bias.  A and Bt k-major, pre-rounded tf32.
// EPI 1: exact GELU(+round)  2: +residual  3: QKV+RoPE scatter
// EPI 4: split-K partial store (grid.x doubled; bx>>3 selects K-half;
//        half 0 -> C, half 1 -> O2; no bias)
// K = row stride; Klen = K extent this block reduces over.
// 3-stage cp.async pipeline, ONE barrier per chunk (2 groups in flight).
#define STR36 36
#define TILE_BYTES (128 * STR36 * 4)      // 18432
#define BUF_BYTES (2 * TILE_BYTES)        // 36864 per stage (A+B)
#define GEMM_SMEM (3 * BUF_BYTES)         // 110592

template <int EPI>
__global__ void __launch_bounds__(256, 2) gemm_mma(
    const float* __restrict__ A, const float* __restrict__ Bt,
    const float* __restrict__ bias, float* __restrict__ C,
    const float* __restrict__ R, float* __restrict__ O2,
    float* __restrict__ O3, int K, int Klen, int N) {
    extern __shared__ char smem[];
    const int tid = threadIdx.x;
    const int wid = tid >> 5, lane = tid & 31;
    const int g = lane >> 2, t4 = lane & 3;
    const int warp_m = wid & 3, warp_n = wid >> 2;

    uint32_t sb = smem_u32(smem);
    int bxn = blockIdx.x, koff = 0;
    if (EPI == 4) { bxn = blockIdx.x & 7; koff = (blockIdx.x >> 3) * Klen; }
    const float* Ag = A + (size_t)blockIdx.y * 128 * K + koff;
    const float* Bg = Bt + (size_t)bxn * 128 * K + koff;

    float acc[2][8][4];
#pragma unroll
    for (int i = 0; i < 2; i++)
#pragma unroll
        for (int j = 0; j < 8; j++)
#pragma unroll
            for (int t = 0; t < 4; t++) acc[i][j][t] = 0.f;

    auto prefetch = [&](int ck, int buf) {
        uint32_t as = sb + buf * BUF_BYTES;
        uint32_t bs = as + TILE_BYTES;
#pragma unroll
        for (int t = 0; t < 4; t++) {
            int slot = tid + t * 256;
            int r = slot >> 3, kq = slot & 7;
            uint32_t so = (uint32_t)(r * STR36 + kq * 4) * 4;
            cp16(as + so, Ag + (size_t)r * K + ck * 32 + kq * 4);
            cp16(bs + so, Bg + (size_t)r * K + ck * 32 + kq * 4);
        }
    };

    const int a_lrow = lane & 15;
    const int a_kofs = ((lane >> 4) << 2);
    const int b_nofs = (lane & 7) + ((lane >> 4) << 3);
    const int b_kofs = (((lane >> 3) & 1) << 2);

    auto compute = [&](int buf) {
        uint32_t as = sb + buf * BUF_BYTES;
        uint32_t bs = as + TILE_BYTES;
#pragma unroll
        for (int ks = 0; ks < 4; ks++) {
            int k0 = ks * 8;
            uint32_t a[2][4];
#pragma unroll
            for (int i = 0; i < 2; i++) {
                uint32_t addr = as +
                    (uint32_t)((warp_m * 32 + i * 16 + a_lrow) * STR36 + k0 + a_kofs) * 4;
                ldsm4(a[i][0], a[i][1], a[i][2], a[i][3], addr);
            }
#pragma unroll
            for (int j2 = 0; j2 < 4; j2++) {
                uint32_t b0, b1, b2, b3;
                uint32_t baddr = bs +
                    (uint32_t)((warp_n * 64 + j2 * 16 + b_nofs) * STR36 + k0 + b_kofs) * 4;
                ldsm4(b0, b1, b2, b3, baddr);
#pragma unroll
                for (int i = 0; i < 2; i++) {
                    mma16n8k8(acc[i][2 * j2 + 0], a[i][0], a[i][1], a[i][2], a[i][3], b0, b1);
                    mma16n8k8(acc[i][2 * j2 + 1], a[i][0], a[i][1], a[i][2], a[i][3], b2, b3);
                }
            }
        }
    };

    // one-barrier-per-chunk 3-stage pipeline (2 groups in flight):
    //   cp_wait(ck landed) ; sync ; prefetch(ck+2 -> buffer (ck-1)%3) ; compute(ck)
    const int nch = Klen / 32;
    prefetch(0, 0);
    cp_commit();
    prefetch(1, 1);
    cp_commit();
    int s2 = 2;
    for (int ck = 0; ck < nch; ck++) {
        if (ck + 1 < nch) cp_wait<1>(); else cp_wait<0>();
        __syncthreads();
        if (ck + 2 < nch) {
            prefetch(ck + 2, s2);
            cp_commit();
            if (++s2 == 3) s2 = 0;
        }
        compute(ck % 3);
    }

    // ---------------- epilogue ----------------
    if (EPI <= 2) {
        const int colb = blockIdx.x * 128 + warp_n * 64;
        const size_t row0 = (size_t)blockIdx.y * 128 + warp_m * 32 + g;
#pragma unroll
        for (int i = 0; i < 2; i++) {
            size_t r0 = row0 + i * 16;
#pragma unroll
            for (int j = 0; j < 8; j++) {
                int c = colb + j * 8 + t4 * 2;
                float b0 = bias[c], b1 = bias[c + 1];
#pragma unroll
                for (int half = 0; half < 2; half++) {
                    size_t r = r0 + half * 8;
                    float v0 = acc[i][j][half * 2 + 0] + b0;
                    float v1 = acc[i][j][half * 2 + 1] + b1;
                    if (EPI == 1) {
                        v0 = rndf(0.5f * v0 * (1.0f + erff(v0 * 0.70710678118654752f)));
                        v1 = rndf(0.5f * v1 * (1.0f + erff(v1 * 0.70710678118654752f)));
                    }
                    if (EPI == 2) {
                        const float2 rr = *(const float2*)(R + r * N + c);
                        v0 += rr.x; v1 += rr.y;
                    }
                    float2 o; o.x = v0; o.y = v1;
                    *(float2*)(C + r * N + c) = o;
                }
            }
        }
    } else if (EPI == 4) {
        // ---- split-K partial store (raw acc, no bias) ----
        float* Cs = (blockIdx.x < 8) ? C : O2;
        const int colb = bxn * 128 + warp_n * 64;
        const size_t row0 = (size_t)blockIdx.y * 128 + warp_m * 32 + g;
#pragma unroll
        for (int i = 0; i < 2; i++) {
            size_t r0 = row0 + i * 16;
#pragma unroll
            for (int j = 0; j < 8; j++) {
                int c = colb + j * 8 + t4 * 2;
#pragma unroll
                for (int half = 0; half < 2; half++) {
                    size_t r = r0 + half * 8;
                    float2 o;
                    o.x = acc[i][j][half * 2 + 0];
                    o.y = acc[i][j][half * 2 + 1];
                    *(float2*)(Cs + r * N + c) = o;
                }
            }
        }
    } else {
        // ---- fused QKV + RoPE + window scatter (EPI == 3) ----
        const int bx = blockIdx.x;
        const int mat = bx >> 3;                      // 0=q 1=k 2=v
        const int hh = ((bx & 7) << 1) + warp_n;      // head 0..15
        int wh_[2][2], s_[2][2], ry_[2][2], cx_[2][2];
#pragma unroll
        for (int i = 0; i < 2; i++)
#pragma unroll
            for (int half = 0; half < 2; half++) {
                int rr = blockIdx.y * 128 + warp_m * 32 + g + i * 16 + half * 8;
                int b_ = rr / 5184, rem = rr - b_ * 5184;
                int y = rem / 72, x = rem - y * 72;
                int wi = y / 24, ry = y - wi * 24;
                int wj = x / 24, cx = x - wj * 24;
                wh_[i][half] = (b_ * 9 + wi * 3 + wj) * 16 + hh;
                s_[i][half] = ry * 24 + cx;
                ry_[i][half] = ry;
                cx_[i][half] = cx;
            }
#pragma unroll
        for (int j = 0; j < 8; j++) {
            const int d = j * 8 + t4 * 2;             // 0..62 even
            const int p = j * 4 + t4;                 // pair index 0..31
            const int jx = p & 15;
            const int xy = p >> 4;
            const float freq = exp2f(-0.830482023722f * (float)jx);
            const int cglob = bx * 128 + warp_n * 64 + d;
            const float b0 = bias[cglob], b1 = bias[cglob + 1];
#pragma unroll
            for (int i = 0; i < 2; i++)
#pragma unroll
                for (int half = 0; half < 2; half++) {
                    float v0 = acc[i][j][half * 2 + 0] + b0;
                    float v1 = acc[i][j][half * 2 + 1] + b1;
                    if (mat == 2) {
                        size_t vb = ((size_t)wh_[i][half] * HD + d) * S_WIN + s_[i][half];
                        O3[vb] = rndf(v0);
                        O3[vb + S_WIN] = rndf(v1);
                    } else {
                        float pos = (xy ? (float)ry_[i][half] : (float)cx_[i][half])
                                    * (1.0f / 3.0f);
                        float sn, cs;
                        __sincosf(pos * freq, &sn, &cs);
                        float o0 = v0 * cs - v1 * sn;
                        float o1 = v1 * cs + v0 * sn;
                        if (mat == 0) { o0 *= 0.125f; o1 *= 0.125f; }
                        float* dstp = (mat == 0) ? C : O2;
                        size_t off = ((size_t)wh_[i][half] * S_WIN + s_[i][half]) * HD + d;
                        float2 o; o.x = rndf(o0); o.y = rndf(o1);
                        *(float2*)(dstp + off) = o;
                    }
                }
        }
    }
}

// ---------------- split-K reduce: out += p0 + p1 + bias ----------------------
__global__ void splitk_reduce(const float* __restrict__ p0, const float* __restrict__ p1,
                              const float* __restrict__ b, float* __restrict__ out) {
    size_t i = ((size_t)blockIdx.x * 256 + threadIdx.x) * 4;
    int c = (int)(i & (HS - 1));
    float4 a0 = *(const float4*)(p0 + i);
    float4 a1 = *(const float4*)(p1 + i);
    float4 oo = *(const float4*)(out + i);
    oo.x += a0.x + a1.x + b[c];
    oo.y += a0.y + a1.y + b[c + 1];
    oo.z += a0.z + a1.z + b[c + 2];
    oo.w += a0.w + a1.w + b[c + 3];
    *(float4*)(out + i) = oo;
}

// ---------------- ALL weight transposes + bias concat in ONE launch ---------
__global__ void transpose_all(const float* __restrict__ wq, const float* __restrict__ wk,
                              const float* __restrict__ wv, const float* __restrict__ wo,
                              const float* __restrict__ w1, const float* __restrict__ w2,
                              float* __restrict__ wqkvT, float* __restrict__ woT,
                              float* __restrict__ w1T, float* __restrict__ w2T,
                              const float* __restrict__ bq, const float* __restrict__ bk,
                              const float* __restrict__ bv, float* __restrict__ bqkv) {
    __shared__ float t[32][33];
    int id = blockIdx.x;
    if (id == 12288) {
        int tid = threadIdx.y * 32 + threadIdx.x;
#pragma unroll
        for (int it = 0; it < 12; it++) {
            int i = tid + it * 256;
            if (i < HS) bqkv[i] = bq[i];
            else if (i < 2 * HS) bqkv[i] = bk[i - HS];
            else bqkv[i] = bv[i - 2 * HS];
        }
        return;
    }
    const float* in;
    float* out;
    int Rr, Cc, bx, by;
    if (id < 4096) {
        int seg = id >> 10, l = id & 1023;
        in = (seg == 0) ? wq : (seg == 1) ? wk : (seg == 2) ? wv : wo;
        out = (seg == 3) ? woT : wqkvT + (size_t)seg * HS * HS;
        Rr = HS; Cc = HS;
        bx = (l & 31) * 32; by = (l >> 5) * 32;
    } else if (id < 8192) {
        int l = id - 4096;
        in = w1; out = w1T; Rr = HS; Cc = 4096;
        bx = (l & 127) * 32; by = (l >> 7) * 32;
    } else {
        int l = id - 8192;
        in = w2; out = w2T; Rr = 4096; Cc = HS;
        bx = (l & 31) * 32; by = (l >> 5) * 32;
    }
    int x = bx + threadIdx.x;
    int y = by + threadIdx.y;
#pragma unroll
    for (int i = 0; i < 32; i += 8)
        t[threadIdx.y + i][threadIdx.x] = in[(size_t)(y + i) * Cc + x];
    __syncthreads();
#pragma unroll
    for (int i = 0; i < 32; i += 8)
        out[(size_t)(bx + threadIdx.y + i) * Rr + by + threadIdx.x] =
            rndf(t[threadIdx.x][threadIdx.y + i]);
}

// ---------------- LayerNorm (tf32-rounded output) ----------------------------
__global__ void ln_kernel(const float* __restrict__ x, const float* __restrict__ g,
                          const float* __restrict__ b, float* __restrict__ out) {
    int row = blockIdx.x;
    int tid = threadIdx.x;
    const float* xr = x + (size_t)row * HS;
    float v[4];
    float s = 0.f, sq = 0.f;
#pragma unroll
    for (int i = 0; i < 4; i++) {
        v[i] = xr[tid + i * 256];
        s += v[i];
        sq += v[i] * v[i];
    }
#pragma unroll
    for (int o = 16; o; o >>= 1) {
        s  += __shfl_xor_sync(0xffffffffu, s, o);
        sq += __shfl_xor_sync(0xffffffffu, sq, o);
    }
    __shared__ float rs[8], rq[8];
    __shared__ float mean_s, rstd_s;
    if ((tid & 31) == 0) { rs[tid >> 5] = s; rq[tid >> 5] = sq; }
    __syncthreads();
    if (tid == 0) {
        float a = 0.f, c = 0.f;
        for (int k = 0; k < 8; k++) { a += rs[k]; c += rq[k]; }
        float m = a * (1.f / HS);
        float var = c * (1.f / HS) - m * m;
        mean_s = m;
        rstd_s = rsqrtf(var + 1e-6f);
    }
    __syncthreads();
    float m = mean_s, r = rstd_s;
    float* orow = out + (size_t)row * HS;
#pragma unroll
    for (int i = 0; i < 4; i++) {
        int c = tid + i * 256;
        orow[c] = rndf((v[i] - m) * r * g[c] + b[c]);
    }
}

// ================= fused flash attention per (wh, 64-q-row block) ===========
// grid (9, 288), 256 threads (8 warps: 2m x 4n, warp tile 32x16).
// 3 CTAs/SM: single-buffered K and V; P tile REUSES the K buffer (K is dead
// after S=QK^T, and the red_max barrier separates last K read from P write).
#define FL_STR 68
#define FL_TILE_B (64 * FL_STR * 4)       // 17408
#define FL_Q 0
#define FL_KP FL_TILE_B                   // K tile, then P tile
#define FL_V (2 * FL_TILE_B)
#define FL_RED (3 * FL_TILE_B)
#define FL_SMEM (3 * FL_TILE_B + 2048)    // 54272 -> 3 CTAs/SM

__global__ void __launch_bounds__(256, 3) flash_attn(
    const float* __restrict__ qw, const float* __restrict__ kw,
    const float* __restrict__ vwT, float* __restrict__ of) {
    extern __shared__ char smem[];
    uint32_t sb = smem_u32(smem);
    const int tid = threadIdx.x;
    const int wid = tid >> 5, lane = tid & 31;
    const int g = lane >> 2, t4 = lane & 3;
    const int warp_m = wid >> 2, warp_n = wid & 3;
    const int wh = blockIdx.y, qb = blockIdx.x;

    const float* Qg = qw + ((size_t)wh * S_WIN + qb * 64) * HD;
    const float* Kg = kw + (size_t)wh * S_WIN * HD;
    const float* Vg = vwT + (size_t)wh * HD * S_WIN;

    auto ldK = [&](int kb) {
#pragma unroll
        for (int t = 0; t < 4; t++) {
            int slot = tid + t * 256;
            int r = slot >> 4, kq = slot & 15;
            cp16(sb + FL_KP + (uint32_t)(r * FL_STR + kq * 4) * 4,
                 Kg + (size_t)(kb * 64 + r) * HD + kq * 4);
        }
    };
    auto ldV = [&](int kb) {
#pragma unroll
        for (int t = 0; t < 4; t++) {
            int slot = tid + t * 256;
            int d = slot >> 4, sq = slot & 15;
            cp16(sb + FL_V + (uint32_t)(d * FL_STR + sq * 4) * 4,
                 Vg + (size_t)d * S_WIN + kb * 64 + sq * 4);
        }
    };

#pragma unroll
    for (int t = 0; t < 4; t++) {
        int slot = tid + t * 256;
        int r = slot >> 4, kq = slot & 15;
        cp16(sb + FL_Q + (uint32_t)(r * FL_STR + kq * 4) * 4,
             Qg + (size_t)r * HD + kq * 4);
    }
    ldK(0);
    ldV(0);
    cp_commit();

    float m_[2][2], l_[2][2], Oa[2][2][4];
#pragma unroll
    for (int i = 0; i < 2; i++)
#pragma unroll
        for (int hf = 0; hf < 2; hf++) { m_[i][hf] = -1e30f; l_[i][hf] = 0.f; }
#pragma unroll
    for (int i = 0; i < 2; i++)
#pragma unroll
        for (int j = 0; j < 2; j++)
#pragma unroll
            for (int t = 0; t < 4; t++) Oa[i][j][t] = 0.f;

    float* red_max = (float*)(smem + FL_RED);   // [4][64]
    float* red_sum = red_max + 256;             // [4][64]
    float* Pt = (float*)(smem + FL_KP);         // P overwrites K tile
    const uint32_t Kt = sb + FL_KP;
    const uint32_t Vt = sb + FL_V;

    const int a_lrow = lane & 15;
    const int a_kofs = ((lane >> 4) << 2);
    const int b_nofs = (lane & 7) + ((lane >> 4) << 3);
    const int b_kofs = (((lane >> 3) & 1) << 2);

    const int rloc0 = warp_m * 32 + g;

    for (int kb = 0; kb < 9; kb++) {
        cp_wait<0>();
        __syncthreads();

        // ---- S = Q @ K^T ----
        float S[2][2][4];
#pragma unroll
        for (int i = 0; i < 2; i++)
#pragma unroll
            for (int j = 0; j < 2; j++)
#pragma unroll
                for (int t = 0; t < 4; t++) S[i][j][t] = 0.f;
#pragma unroll
        for (int ks = 0; ks < 8; ks++) {
            int k0 = ks * 8;
            uint32_t a[2][4];
#pragma unroll
            for (int i = 0; i < 2; i++)
                ldsm4(a[i][0], a[i][1], a[i][2], a[i][3],
                      sb + FL_Q + (uint32_t)((warp_m * 32 + i * 16 + a_lrow) * FL_STR + k0 + a_kofs) * 4);
            uint32_t b0, b1, b2, b3;
            ldsm4(b0, b1, b2, b3,
                  Kt + (uint32_t)((warp_n * 16 + b_nofs) * FL_STR + k0 + b_kofs) * 4);
#pragma unroll
            for (int i = 0; i < 2; i++) {
                mma16n8k8(S[i][0], a[i][0], a[i][1], a[i][2], a[i][3], b0, b1);
                mma16n8k8(S[i][1], a[i][0], a[i][1], a[i][2], a[i][3], b2, b3);
            }
        }

        // ---- row max ----
        float mx[2][2];
#pragma unroll
        for (int i = 0; i < 2; i++)
#pragma unroll
            for (int hf = 0; hf < 2; hf++) {
                float v = fmaxf(fmaxf(S[i][0][hf * 2], S[i][0][hf * 2 + 1]),
                                fmaxf(S[i][1][hf * 2], S[i][1][hf * 2 + 1]));
                v = fmaxf(v, __shfl_xor_sync(0xffffffffu, v, 1));
                v = fmaxf(v, __shfl_xor_sync(0xffffffffu, v, 2));
                mx[i][hf] = v;
            }
        if (t4 == 0) {
#pragma unroll
            for (int i = 0; i < 2; i++)
#pragma unroll
                for (int hf = 0; hf < 2; hf++)
                    red_max[warp_n * 64 + rloc0 + i * 16 + hf * 8] = mx[i][hf];
        }
        __syncthreads();   // also: last K reads done -> P may overwrite K tile

        float alpha[2][2];
#pragma unroll
        for (int i = 0; i < 2; i++)
#pragma unroll
            for (int hf = 0; hf < 2; hf++) {
                int r = rloc0 + i * 16 + hf * 8;
                float tm = fmaxf(fmaxf(red_max[r], red_max[64 + r]),
                                 fmaxf(red_max[128 + r], red_max[192 + r]));
                float mn = fmaxf(m_[i][hf], tm);
                alpha[i][hf] = __expf(m_[i][hf] - mn);
                m_[i][hf] = mn;
            }

        float rs[2][2];
#pragma unroll
        for (int i = 0; i < 2; i++)
#pragma unroll
            for (int hf = 0; hf < 2; hf++) {
                float m = m_[i][hf];
                float e0 = __expf(S[i][0][hf * 2]     - m);
                float e1 = __expf(S[i][0][hf * 2 + 1] - m);
                float e2 = __expf(S[i][1][hf * 2]     - m);
                float e3 = __expf(S[i][1][hf * 2 + 1] - m);
                S[i][0][hf * 2] = e0; S[i][0][hf * 2 + 1] = e1;
                S[i][1][hf * 2] = e2; S[i][1][hf * 2 + 1] = e3;
                float v = (e0 + e1) + (e2 + e3);
                v += __shfl_xor_sync(0xffffffffu, v, 1);
                v += __shfl_xor_sync(0xffffffffu, v, 2);
                rs[i][hf] = v;
            }
        if (t4 == 0) {
#pragma unroll
            for (int i = 0; i < 2; i++)
#pragma unroll
                for (int hf = 0; hf < 2; hf++)
                    red_sum[warp_n * 64 + rloc0 + i * 16 + hf * 8] = rs[i][hf];
        }
#pragma unroll
        for (int i = 0; i < 2; i++)
#pragma unroll
            for (int hf = 0; hf < 2; hf++) {
                int r = rloc0 + i * 16 + hf * 8;
#pragma unroll
                for (int j = 0; j < 2; j++) {
                    float2 o;
                    o.x = rndf(S[i][j][hf * 2]);
                    o.y = rndf(S[i][j][hf * 2 + 1]);
                    *(float2*)(Pt + r * FL_STR + warp_n * 16 + j * 8 + t4 * 2) = o;
                }
            }
        __syncthreads();

        // ---- l update + rescale O ----
#pragma unroll
        for (int i = 0; i < 2; i++)
#pragma unroll
            for (int hf = 0; hf < 2; hf++) {
                int r = rloc0 + i * 16 + hf * 8;
                float tot = ((red_sum[r] + red_sum[64 + r]) +
                             (red_sum[128 + r] + red_sum[192 + r]));
                l_[i][hf] = l_[i][hf] * alpha[i][hf] + tot;
                float a = alpha[i][hf];
#pragma unroll
                for (int j = 0; j < 2; j++) {
                    Oa[i][j][hf * 2]     *= a;
                    Oa[i][j][hf * 2 + 1] *= a;
                }
            }

        // ---- O += P @ V ----
#pragma unroll
        for (int ks = 0; ks < 8; ks++) {
            int k0 = ks * 8;
            uint32_t a[2][4];
#pragma unroll
            for (int i = 0; i < 2; i++)
                ldsm4(a[i][0], a[i][1], a[i][2], a[i][3],
                      sb + FL_KP + (uint32_t)((warp_m * 32 + i * 16 + a_lrow) * FL_STR + k0 + a_kofs) * 4);
            uint32_t b0, b1, b2, b3;
            ldsm4(b0, b1, b2, b3,
                  Vt + (uint32_t)((warp_n * 16 + b_nofs) * FL_STR + k0 + b_kofs) * 4);
#pragma unroll
            for (int i = 0; i < 2; i++) {
                mma16n8k8(Oa[i][0], a[i][0], a[i][1], a[i][2], a[i][3], b0, b1);
                mma16n8k8(Oa[i][1], a[i][0], a[i][1], a[i][2], a[i][3], b2, b3);
            }
        }
        __syncthreads();   // P and V fully consumed -> next loads may overwrite

        if (kb + 1 < 9) {
            ldK(kb + 1);
            ldV(kb + 1);
            cp_commit();
        }
    }

    int h = wh & 15, w = wh >> 4;
    int bb = w / 9, wi = (w % 9) / 3, wj = w % 3;
#pragma unroll
    for (int i = 0; i < 2; i++)
#pragma unroll
        for (int hf = 0; hf < 2; hf++) {
            int s = qb * 64 + rloc0 + i * 16 + hf * 8;
            int r = s / 24, c = s - r * 24;
            int tok = bb * 5184 + (wi * 24 + r) * 72 + (wj * 24 + c);
            float inv = 1.f / l_[i][hf];
            float* orow = of + (size_t)tok * HS + h * HD;
#pragma unroll
            for (int j = 0; j < 2; j++) {
                float2 o;
                o.x = rndf(Oa[i][j][hf * 2]     * inv);
                o.y = rndf(Oa[i][j][hf * 2 + 1] * inv);
                *(float2*)(orow + warp_n * 16 + j * 8 + t4 * 2) = o;
            }
        }
}

// ---------------- host launch -----------------------------------------------
extern "C" void kernel_launch(void* const* d_in, const int* in_sizes, int n_in,
                              void* d_out, int out_size) {
    const float* hidden = (const float*)d_in[0];
    const float* ln1_g  = (const float*)d_in[1];
    const float* ln1_b  = (const float*)d_in[2];
    const float* wq = (const float*)d_in[3];
    const float* bq = (const float*)d_in[4];
    const float* wk = (const float*)d_in[5];
    const float* bk = (const float*)d_in[6];
    const float* wv = (const float*)d_in[7];
    const float* bv = (const float*)d_in[8];
    const float* wo = (const float*)d_in[9];
    const float* bo = (const float*)d_in[10];
    const float* ln2_g = (const float*)d_in[11];
    const float* ln2_b = (const float*)d_in[12];
    const float* w1 = (const float*)d_in[13];
    const float* b1 = (const float*)d_in[14];
    const float* w2 = (const float*)d_in[15];
    const float* b2 = (const float*)d_in[16];
    float* out = (float*)d_out;

    float *xn, *qw, *kw, *vwT, *of, *yn, *hm;
    float *wqkvT, *bqkv, *woT, *w1T, *w2T;
    cudaGetSymbolAddress((void**)&xn, g_xn);
    cudaGetSymbolAddress((void**)&qw, g_qw);
    cudaGetSymbolAddress((void**)&kw, g_kw);
    cudaGetSymbolAddress((void**)&vwT, g_vwT);
    cudaGetSymbolAddress((void**)&of, g_of);
    cudaGetSymbolAddress((void**)&yn, g_yn);
    cudaGetSymbolAddress((void**)&hm, g_hm);
    cudaGetSymbolAddress((void**)&wqkvT, g_wqkvT);
    cudaGetSymbolAddress((void**)&bqkv, g_bqkv);
    cudaGetSymbolAddress((void**)&woT, g_woT);
    cudaGetSymbolAddress((void**)&w1T, g_w1T);
    cudaGetSymbolAddress((void**)&w2T, g_w2T);

    cudaFuncSetAttribute(gemm_mma<1>, cudaFuncAttributeMaxDynamicSharedMemorySize, GEMM_SMEM);
    cudaFuncSetAttribute(gemm_mma<2>, cudaFuncAttributeMaxDynamicSharedMemorySize, GEMM_SMEM);
    cudaFuncSetAttribute(gemm_mma<3>, cudaFuncAttributeMaxDynamicSharedMemorySize, GEMM_SMEM);
    cudaFuncSetAttribute(gemm_mma<4>, cudaFuncAttributeMaxDynamicSharedMemorySize, GEMM_SMEM);
    cudaFuncSetAttribute(flash_attn, cudaFuncAttributeMaxDynamicSharedMemorySize, FL_SMEM);

    // 0) all transposes (+ tf32 round) + bias concat in one launch; LN1 separate
    transpose_all<<<12289, dim3(32, 8)>>>(wq, wk, wv, wo, w1, w2,
                                          wqkvT, woT, w1T, w2T,
                                          bq, bk, bv, bqkv);
    ln_kernel<<<N_TOK, 256>>>(hidden, ln1_g, ln1_b, xn);

    // 1) fused QKV projection + RoPE + window scatter
    gemm_mma<3><<<dim3(3 * HS / 128, N_TOK / 128), 256, GEMM_SMEM>>>(
        xn, wqkvT, bqkv, qw, nullptr, kw, vwT, HS, HS, 3 * HS);

    // 2) fused flash attention (3 CTAs/SM)
    flash_attn<<<dim3(9, NWH), 256, FL_SMEM>>>(qw, kw, vwT, of);

    // 3) O projection + residual -> x (in d_out)
    dim3 gProj(HS / 128, N_TOK / 128);
    gemm_mma<2><<<gProj, 256, GEMM_SMEM>>>(of, woT, bo, out, hidden, nullptr, nullptr,
                                           HS, HS, HS);

    // 4) LN2
    ln_kernel<<<N_TOK, 256>>>(out, ln2_g, ln2_b, yn);

    // 5) MLP1 (GELU epilogue)
    gemm_mma<1><<<dim3(4096 / 128, N_TOK / 128), 256, GEMM_SMEM>>>(
        yn, w1T, b1, hm, nullptr, nullptr, nullptr, HS, HS, 4096);

    // 6) MLP2: single-launch split-K=2 (bx>=8 -> K-half 1) + fused reduce
    gemm_mma<4><<<dim3(16, N_TOK / 128), 256, GEMM_SMEM>>>(
        hm, w2T, nullptr, xn, nullptr, of, nullptr, 4096, 2048, HS);
    splitk_reduce<<<N_TOK * HS / 1024, 256>>>(xn, of, b2, out);
}

// round 15
// speedup vs baseline: 1.0024x; 1.0024x over previous
#include <cuda_runtime.h>
#include <cstdint>
#include <math.h>

#define N_TOK 10368          // 2*72*72
#define HS    1024
#define NWH   288            // 18 windows * 16 heads
#define S_WIN 576            // 24*24
#define HD    64

// ---------------- scratch (static device arrays; no runtime allocation) ----
__device__ float g_xn[N_TOK * HS];              // LN1 out; later split-K partial 0
__device__ float g_qw[NWH * S_WIN * HD];
__device__ float g_kw[NWH * S_WIN * HD];
__device__ float g_vwT[NWH * HD * S_WIN];       // [wh][d][s]
__device__ float g_of[N_TOK * HS];              // attn out; later split-K partial 1
__device__ float g_yn[N_TOK * HS];
__device__ float g_hm[(size_t)N_TOK * 4096];
// transposed (k-major) tf32-rounded weights
__device__ float g_wqkvT[3 * HS * HS];          // [3072][1024]
__device__ float g_bqkv[3 * HS];
__device__ float g_woT[HS * HS];
__device__ float g_w1T[HS * 4096];
__device__ float g_w2T[HS * 4096];

// ============================ helpers =======================================
__device__ __forceinline__ uint32_t smem_u32(const void* p) {
    uint32_t a;
    asm("{ .reg .u64 t; cvta.to.shared.u64 t, %1; cvt.u32.u64 %0, t; }"
        : "=r"(a) : "l"(p));
    return a;
}

__device__ __forceinline__ float rndf(float x) {   // round fp32 -> tf32-representable
    uint32_t r;
    asm("cvt.rna.tf32.f32 %0, %1;" : "=r"(r) : "f"(x));
    return __uint_as_float(r);
}

__device__ __forceinline__ void cp16(uint32_t dst, const void* src) {
    asm volatile("cp.async.cg.shared.global [%0], [%1], 16;"
                 :: "r"(dst), "l"(src) : "memory");
}
__device__ __forceinline__ void cp_commit() {
    asm volatile("cp.async.commit_group;" ::: "memory");
}
template <int N>
__device__ __forceinline__ void cp_wait() {
    asm volatile("cp.async.wait_group %0;" :: "n"(N) : "memory");
}

__device__ __forceinline__ void mma16n8k8(float* c, uint32_t a0, uint32_t a1,
                                          uint32_t a2, uint32_t a3,
                                          uint32_t b0, uint32_t b1) {
    asm volatile(
        "mma.sync.aligned.m16n8k8.row.col.f32.tf32.tf32.f32 "
        "{%0,%1,%2,%3}, {%4,%5,%6,%7}, {%8,%9}, {%0,%1,%2,%3};"
        : "+f"(c[0]), "+f"(c[1]), "+f"(c[2]), "+f"(c[3])
        : "r"(a0), "r"(a1), "r"(a2), "r"(a3), "r"(b0), "r"(b1));
}

__device__ __forceinline__ void ldsm4(uint32_t& r0, uint32_t& r1, uint32_t& r2,
                                      uint32_t& r3, uint32_t addr) {
    asm volatile("ldmatrix.sync.aligned.m8n8.x4.shared.b16 {%0,%1,%2,%3}, [%4];"
                 : "=r"(r0), "=r"(r1), "=r"(r2), "=r"(r3) : "r"(addr));
}

// ============================ tf32 mma.sync GEMM ============================
// C[M,N] = A[M,K] @ Bt[n][k]^T + bias.  A and Bt k-major, pre-rounded tf32.
// EPI 1: exact GELU(+round)  2: +residual  3: QKV+RoPE scatter
// EPI 4: split-K partial store (grid.x doubled; bx>>3 selects K-half;
//        half 0 -> C, half 1 -> O2; no bias)
// K = row stride; Klen = K extent this block reduces over.
// 3-stage cp.async pipeline, ONE barrier per chunk (2 groups in flight).
#define STR36 36
#define TILE_BYTES (128 * STR36 * 4)      // 18432
#define BUF_BYTES (2 * TILE_BYTES)        // 36864 per stage (A+B)
#define GEMM_SMEM (3 * BUF_BYTES)         // 110592

template <int EPI>
__global__ void __launch_bounds__(256, 2) gemm_mma(
    const float* __restrict__ A, const float* __restrict__ Bt,
    const float* __restrict__ bias, float* __restrict__ C,
    const float* __restrict__ R, float* __restrict__ O2,
    float* __restrict__ O3, int K, int Klen, int N) {
    extern __shared__ char smem[];
    const int tid = threadIdx.x;
    const int wid = tid >> 5, lane = tid & 31;
    const int g = lane >> 2, t4 = lane & 3;
    const int warp_m = wid & 3, warp_n = wid >> 2;

    uint32_t sb = smem_u32(smem);
    int bxn = blockIdx.x, koff = 0;
    if (EPI == 4) { bxn = blockIdx.x & 7; koff = (blockIdx.x >> 3) * Klen; }
    const float* Ag = A + (size_t)blockIdx.y * 128 * K + koff;
    const float* Bg = Bt + (size_t)bxn * 128 * K + koff;

    float acc[2][8][4];
#pragma unroll
    for (int i = 0; i < 2; i++)
#pragma unroll
        for (int j = 0; j < 8; j++)
#pragma unroll
            for (int t = 0; t < 4; t++) acc[i][j][t] = 0.f;

    auto prefetch = [&](int ck, int buf) {
        uint32_t as = sb + buf * BUF_BYTES;
        uint32_t bs = as + TILE_BYTES;
#pragma unroll
        for (int t = 0; t < 4; t++) {
            int slot = tid + t * 256;
            int r = slot >> 3, kq = slot & 7;
            uint32_t so = (uint32_t)(r * STR36 + kq * 4) * 4;
            cp16(as + so, Ag + (size_t)r * K + ck * 32 + kq * 4);
            cp16(bs + so, Bg + (size_t)r * K + ck * 32 + kq * 4);
        }
    };

    const int a_lrow = lane & 15;
    const int a_kofs = ((lane >> 4) << 2);
    const int b_nofs = (lane & 7) + ((lane >> 4) << 3);
    const int b_kofs = (((lane >> 3) & 1) << 2);

    auto compute = [&](int buf) {
        uint32_t as = sb + buf * BUF_BYTES;
        uint32_t bs = as + TILE_BYTES;
#pragma unroll
        for (int ks = 0; ks < 4; ks++) {
            int k0 = ks * 8;
            uint32_t a[2][4];
#pragma unroll
            for (int i = 0; i < 2; i++) {
                uint32_t addr = as +
                    (uint32_t)((warp_m * 32 + i * 16 + a_lrow) * STR36 + k0 + a_kofs) * 4;
                ldsm4(a[i][0], a[i][1], a[i][2], a[i][3], addr);
            }
#pragma unroll
            for (int j2 = 0; j2 < 4; j2++) {
                uint32_t b0, b1, b2, b3;
                uint32_t baddr = bs +
                    (uint32_t)((warp_n * 64 + j2 * 16 + b_nofs) * STR36 + k0 + b_kofs) * 4;
                ldsm4(b0, b1, b2, b3, baddr);
#pragma unroll
                for (int i = 0; i < 2; i++) {
                    mma16n8k8(acc[i][2 * j2 + 0], a[i][0], a[i][1], a[i][2], a[i][3], b0, b1);
                    mma16n8k8(acc[i][2 * j2 + 1], a[i][0], a[i][1], a[i][2], a[i][3], b2, b3);
                }
            }
        }
    };

    // one-barrier-per-chunk 3-stage pipeline (2 groups in flight):
    //   cp_wait(ck landed) ; sync ; prefetch(ck+2 -> buffer (ck-1)%3) ; compute(ck)
    const int nch = Klen / 32;
    prefetch(0, 0);
    cp_commit();
    prefetch(1, 1);
    cp_commit();
    int s2 = 2;
    for (int ck = 0; ck < nch; ck++) {
        if (ck + 1 < nch) cp_wait<1>(); else cp_wait<0>();
        __syncthreads();
        if (ck + 2 < nch) {
            prefetch(ck + 2, s2);
            cp_commit();
            if (++s2 == 3) s2 = 0;
        }
        compute(ck % 3);
    }

    // ---------------- epilogue ----------------
    if (EPI <= 2) {
        const int colb = blockIdx.x * 128 + warp_n * 64;
        const size_t row0 = (size_t)blockIdx.y * 128 + warp_m * 32 + g;
#pragma unroll
        for (int i = 0; i < 2; i++) {
            size_t r0 = row0 + i * 16;
#pragma unroll
            for (int j = 0; j < 8; j++) {
                int c = colb + j * 8 + t4 * 2;
                float b0 = bias[c], b1 = bias[c + 1];
#pragma unroll
                for (int half = 0; half < 2; half++) {
                    size_t r = r0 + half * 8;
                    float v0 = acc[i][j][half * 2 + 0] + b0;
                    float v1 = acc[i][j][half * 2 + 1] + b1;
                    if (EPI == 1) {
                        v0 = rndf(0.5f * v0 * (1.0f + erff(v0 * 0.70710678118654752f)));
                        v1 = rndf(0.5f * v1 * (1.0f + erff(v1 * 0.70710678118654752f)));
                    }
                    if (EPI == 2) {
                        const float2 rr = *(const float2*)(R + r * N + c);
                        v0 += rr.x; v1 += rr.y;
                    }
                    float2 o; o.x = v0; o.y = v1;
                    *(float2*)(C + r * N + c) = o;
                }
            }
        }
    } else if (EPI == 4) {
        // ---- split-K partial store (raw acc, no bias) ----
        float* Cs = (blockIdx.x < 8) ? C : O2;
        const int colb = bxn * 128 + warp_n * 64;
        const size_t row0 = (size_t)blockIdx.y * 128 + warp_m * 32 + g;
#pragma unroll
        for (int i = 0; i < 2; i++) {
            size_t r0 = row0 + i * 16;
#pragma unroll
            for (int j = 0; j < 8; j++) {
                int c = colb + j * 8 + t4 * 2;
#pragma unroll
                for (int half = 0; half < 2; half++) {
                    size_t r = r0 + half * 8;
                    float2 o;
                    o.x = acc[i][j][half * 2 + 0];
                    o.y = acc[i][j][half * 2 + 1];
                    *(float2*)(Cs + r * N + c) = o;
                }
            }
        }
    } else {
        // ---- fused QKV + RoPE + window scatter (EPI == 3) ----
        const int bx = blockIdx.x;
        const int mat = bx >> 3;                      // 0=q 1=k 2=v
        const int hh = ((bx & 7) << 1) + warp_n;      // head 0..15
        int wh_[2][2], s_[2][2], ry_[2][2], cx_[2][2];
#pragma unroll
        for (int i = 0; i < 2; i++)
#pragma unroll
            for (int half = 0; half < 2; half++) {
                int rr = blockIdx.y * 128 + warp_m * 32 + g + i * 16 + half * 8;
                int b_ = rr / 5184, rem = rr - b_ * 5184;
                int y = rem / 72, x = rem - y * 72;
                int wi = y / 24, ry = y - wi * 24;
                int wj = x / 24, cx = x - wj * 24;
                wh_[i][half] = (b_ * 9 + wi * 3 + wj) * 16 + hh;
                s_[i][half] = ry * 24 + cx;
                ry_[i][half] = ry;
                cx_[i][half] = cx;
            }
#pragma unroll
        for (int j = 0; j < 8; j++) {
            const int d = j * 8 + t4 * 2;             // 0..62 even
            const int p = j * 4 + t4;                 // pair index 0..31
            const int jx = p & 15;
            const int xy = p >> 4;
            const float freq = exp2f(-0.830482023722f * (float)jx);
            const int cglob = bx * 128 + warp_n * 64 + d;
            const float b0 = bias[cglob], b1 = bias[cglob + 1];
#pragma unroll
            for (int i = 0; i < 2; i++)
#pragma unroll
                for (int half = 0; half < 2; half++) {
                    float v0 = acc[i][j][half * 2 + 0] + b0;
                    float v1 = acc[i][j][half * 2 + 1] + b1;
                    if (mat == 2) {
                        size_t vb = ((size_t)wh_[i][half] * HD + d) * S_WIN + s_[i][half];
                        O3[vb] = rndf(v0);
                        O3[vb + S_WIN] = rndf(v1);
                    } else {
                        float pos = (xy ? (float)ry_[i][half] : (float)cx_[i][half])
                                    * (1.0f / 3.0f);
                        float sn, cs;
                        __sincosf(pos * freq, &sn, &cs);
                        float o0 = v0 * cs - v1 * sn;
                        float o1 = v1 * cs + v0 * sn;
                        if (mat == 0) { o0 *= 0.125f; o1 *= 0.125f; }
                        float* dstp = (mat == 0) ? C : O2;
                        size_t off = ((size_t)wh_[i][half] * S_WIN + s_[i][half]) * HD + d;
                        float2 o; o.x = rndf(o0); o.y = rndf(o1);
                        *(float2*)(dstp + off) = o;
                    }
                }
        }
    }
}

// ---------------- split-K reduce: out += p0 + p1 + bias ----------------------
__global__ void splitk_reduce(const float* __restrict__ p0, const float* __restrict__ p1,
                              const float* __restrict__ b, float* __restrict__ out) {
    size_t i = ((size_t)blockIdx.x * 256 + threadIdx.x) * 4;
    int c = (int)(i & (HS - 1));
    float4 a0 = *(const float4*)(p0 + i);
    float4 a1 = *(const float4*)(p1 + i);
    float4 oo = *(const float4*)(out + i);
    oo.x += a0.x + a1.x + b[c];
    oo.y += a0.y + a1.y + b[c + 1];
    oo.z += a0.z + a1.z + b[c + 2];
    oo.w += a0.w + a1.w + b[c + 3];
    *(float4*)(out + i) = oo;
}

// ---------------- ALL weight transposes + bias concat in ONE launch ---------
__global__ void transpose_all(const float* __restrict__ wq, const float* __restrict__ wk,
                              const float* __restrict__ wv, const float* __restrict__ wo,
                              const float* __restrict__ w1, const float* __restrict__ w2,
                              float* __restrict__ wqkvT, float* __restrict__ woT,
                              float* __restrict__ w1T, float* __restrict__ w2T,
                              const float* __restrict__ bq, const float* __restrict__ bk,
                              const float* __restrict__ bv, float* __restrict__ bqkv) {
    __shared__ float t[32][33];
    int id = blockIdx.x;
    if (id == 12288) {
        int tid = threadIdx.y * 32 + threadIdx.x;
#pragma unroll
        for (int it = 0; it < 12; it++) {
            int i = tid + it * 256;
            if (i < HS) bqkv[i] = bq[i];
            else if (i < 2 * HS) bqkv[i] = bk[i - HS];
            else bqkv[i] = bv[i - 2 * HS];
        }
        return;
    }
    const float* in;
    float* out;
    int Rr, Cc, bx, by;
    if (id < 4096) {
        int seg = id >> 10, l = id & 1023;
        in = (seg == 0) ? wq : (seg == 1) ? wk : (seg == 2) ? wv : wo;
        out = (seg == 3) ? woT : wqkvT + (size_t)seg * HS * HS;
        Rr = HS; Cc = HS;
        bx = (l & 31) * 32; by = (l >> 5) * 32;
    } else if (id < 8192) {
        int l = id - 4096;
        in = w1; out = w1T; Rr = HS; Cc = 4096;
        bx = (l & 127) * 32; by = (l >> 7) * 32;
    } else {
        int l = id - 8192;
        in = w2; out = w2T; Rr = 4096; Cc = HS;
        bx = (l & 31) * 32; by = (l >> 5) * 32;
    }
    int x = bx + threadIdx.x;
    int y = by + threadIdx.y;
#pragma unroll
    for (int i = 0; i < 32; i += 8)
        t[threadIdx.y + i][threadIdx.x] = in[(size_t)(y + i) * Cc + x];
    __syncthreads();
#pragma unroll
    for (int i = 0; i < 32; i += 8)
        out[(size_t)(bx + threadIdx.y + i) * Rr + by + threadIdx.x] =
            rndf(t[threadIdx.x][threadIdx.y + i]);
}

// ---------------- LayerNorm (tf32-rounded output) ----------------------------
__global__ void ln_kernel(const float* __restrict__ x, const float* __restrict__ g,
                          const float* __restrict__ b, float* __restrict__ out) {
    int row = blockIdx.x;
    int tid = threadIdx.x;
    const float* xr = x + (size_t)row * HS;
    float v[4];
    float s = 0.f, sq = 0.f;
#pragma unroll
    for (int i = 0; i < 4; i++) {
        v[i] = xr[tid + i * 256];
        s += v[i];
        sq += v[i] * v[i];
    }
#pragma unroll
    for (int o = 16; o; o >>= 1) {
        s  += __shfl_xor_sync(0xffffffffu, s, o);
        sq += __shfl_xor_sync(0xffffffffu, sq, o);
    }
    __shared__ float rs[8], rq[8];
    __shared__ float mean_s, rstd_s;
    if ((tid & 31) == 0) { rs[tid >> 5] = s; rq[tid >> 5] = sq; }
    __syncthreads();
    if (tid == 0) {
        float a = 0.f, c = 0.f;
        for (int k = 0; k < 8; k++) { a += rs[k]; c += rq[k]; }
        float m = a * (1.f / HS);
        float var = c * (1.f / HS) - m * m;
        mean_s = m;
        rstd_s = rsqrtf(var + 1e-6f);
    }
    __syncthreads();
    float m = mean_s, r = rstd_s;
    float* orow = out + (size_t)row * HS;
#pragma unroll
    for (int i = 0; i < 4; i++) {
        int c = tid + i * 256;
        orow[c] = rndf((v[i] - m) * r * g[c] + b[c]);
    }
}

// ================= fused flash attention per (wh, 64-q-row block) ===========
// grid (9, 288), 256 threads (8 warps: 2m x 4n, warp tile 32x16).
// 3 CTAs/SM.  Separate P buffer so the NEXT K load issues right after the
// red_max barrier (K dead after S=QK^T) -> K load covered by softmax+PV.
// V load issues after the PV barrier as before.
#define FL_STR 68
#define FL_TILE_B (64 * FL_STR * 4)       // 17408
#define FL_Q 0
#define FL_K FL_TILE_B
#define FL_V (2 * FL_TILE_B)
#define FL_P (3 * FL_TILE_B)
#define FL_RED (4 * FL_TILE_B)
#define FL_SMEM (4 * FL_TILE_B + 2048)    // 71680 -> 3 CTAs/SM (215 KB)

__global__ void __launch_bounds__(256, 3) flash_attn(
    const float* __restrict__ qw, const float* __restrict__ kw,
    const float* __restrict__ vwT, float* __restrict__ of) {
    extern __shared__ char smem[];
    uint32_t sb = smem_u32(smem);
    const int tid = threadIdx.x;
    const int wid = tid >> 5, lane = tid & 31;
    const int g = lane >> 2, t4 = lane & 3;
    const int warp_m = wid >> 2, warp_n = wid & 3;
    const int wh = blockIdx.y, qb = blockIdx.x;

    const float* Qg = qw + ((size_t)wh * S_WIN + qb * 64) * HD;
    const float* Kg = kw + (size_t)wh * S_WIN * HD;
    const float* Vg = vwT + (size_t)wh * HD * S_WIN;

    auto ldK = [&](int kb) {
#pragma unroll
        for (int t = 0; t < 4; t++) {
            int slot = tid + t * 256;
            int r = slot >> 4, kq = slot & 15;
            cp16(sb + FL_K + (uint32_t)(r * FL_STR + kq * 4) * 4,
                 Kg + (size_t)(kb * 64 + r) * HD + kq * 4);
        }
    };
    auto ldV = [&](int kb) {
#pragma unroll
        for (int t = 0; t < 4; t++) {
            int slot = tid + t * 256;
            int d = slot >> 4, sq = slot & 15;
            cp16(sb + FL_V + (uint32_t)(d * FL_STR + sq * 4) * 4,
                 Vg + (size_t)d * S_WIN + kb * 64 + sq * 4);
        }
    };

#pragma unroll
    for (int t = 0; t < 4; t++) {
        int slot = tid + t * 256;
        int r = slot >> 4, kq = slot & 15;
        cp16(sb + FL_Q + (uint32_t)(r * FL_STR + kq * 4) * 4,
             Qg + (size_t)r * HD + kq * 4);
    }
    ldK(0);
    ldV(0);
    cp_commit();

    float m_[2][2], l_[2][2], Oa[2][2][4];
#pragma unroll
    for (int i = 0; i < 2; i++)
#pragma unroll
        for (int hf = 0; hf < 2; hf++) { m_[i][hf] = -1e30f; l_[i][hf] = 0.f; }
#pragma unroll
    for (int i = 0; i < 2; i++)
#pragma unroll
        for (int j = 0; j < 2; j++)
#pragma unroll
            for (int t = 0; t < 4; t++) Oa[i][j][t] = 0.f;

    float* red_max = (float*)(smem + FL_RED);   // [4][64]
    float* red_sum = red_max + 256;             // [4][64]
    float* Pt = (float*)(smem + FL_P);
    const uint32_t Kt = sb + FL_K;
    const uint32_t Vt = sb + FL_V;

    const int a_lrow = lane & 15;
    const int a_kofs = ((lane >> 4) << 2);
    const int b_nofs = (lane & 7) + ((lane >> 4) << 3);
    const int b_kofs = (((lane >> 3) & 1) << 2);

    const int rloc0 = warp_m * 32 + g;

    for (int kb = 0; kb < 9; kb++) {
        cp_wait<0>();
        __syncthreads();

        // ---- S = Q @ K^T ----
        float S[2][2][4];
#pragma unroll
        for (int i = 0; i < 2; i++)
#pragma unroll
            for (int j = 0; j < 2; j++)
#pragma unroll
                for (int t = 0; t < 4; t++) S[i][j][t] = 0.f;
#pragma unroll
        for (int ks = 0; ks < 8; ks++) {
            int k0 = ks * 8;
            uint32_t a[2][4];
#pragma unroll
            for (int i = 0; i < 2; i++)
                ldsm4(a[i][0], a[i][1], a[i][2], a[i][3],
                      sb + FL_Q + (uint32_t)((warp_m * 32 + i * 16 + a_lrow) * FL_STR + k0 + a_kofs) * 4);
            uint32_t b0, b1, b2, b3;
            ldsm4(b0, b1, b2, b3,
                  Kt + (uint32_t)((warp_n * 16 + b_nofs) * FL_STR + k0 + b_kofs) * 4);
#pragma unroll
            for (int i = 0; i < 2; i++) {
                mma16n8k8(S[i][0], a[i][0], a[i][1], a[i][2], a[i][3], b0, b1);
                mma16n8k8(S[i][1], a[i][0], a[i][1], a[i][2], a[i][3], b2, b3);
            }
        }

        // ---- row max ----
        float mx[2][2];
#pragma unroll
        for (int i = 0; i < 2; i++)
#pragma unroll
            for (int hf = 0; hf < 2; hf++) {
                float v = fmaxf(fmaxf(S[i][0][hf * 2], S[i][0][hf * 2 + 1]),
                                fmaxf(S[i][1][hf * 2], S[i][1][hf * 2 + 1]));
                v = fmaxf(v, __shfl_xor_sync(0xffffffffu, v, 1));
                v = fmaxf(v, __shfl_xor_sync(0xffffffffu, v, 2));
                mx[i][hf] = v;
            }
        if (t4 == 0) {
#pragma unroll
            for (int i = 0; i < 2; i++)
#pragma unroll
                for (int hf = 0; hf < 2; hf++)
                    red_max[warp_n * 64 + rloc0 + i * 16 + hf * 8] = mx[i][hf];
        }
        __syncthreads();   // all K reads done -> safe to refill K buffer

        // issue next K load NOW: covered by softmax + P write + PV below
        if (kb + 1 < 9) {
            ldK(kb + 1);
            cp_commit();
        }

        float alpha[2][2];
#pragma unroll
        for (int i = 0; i < 2; i++)
#pragma unroll
            for (int hf = 0; hf < 2; hf++) {
                int r = rloc0 + i * 16 + hf * 8;
                float tm = fmaxf(fmaxf(red_max[r], red_max[64 + r]),
                                 fmaxf(red_max[128 + r], red_max[192 + r]));
                float mn = fmaxf(m_[i][hf], tm);
                alpha[i][hf] = __expf(m_[i][hf] - mn);
                m_[i][hf] = mn;
            }

        float rs[2][2];
#pragma unroll
        for (int i = 0; i < 2; i++)
#pragma unroll
            for (int hf = 0; hf < 2; hf++) {
                float m = m_[i][hf];
                float e0 = __expf(S[i][0][hf * 2]     - m);
                float e1 = __expf(S[i][0][hf * 2 + 1] - m);
                float e2 = __expf(S[i][1][hf * 2]     - m);
                float e3 = __expf(S[i][1][hf * 2 + 1] - m);
                S[i][0][hf * 2] = e0; S[i][0][hf * 2 + 1] = e1;
                S[i][1][hf * 2] = e2; S[i][1][hf * 2 + 1] = e3;
                float v = (e0 + e1) + (e2 + e3);
                v += __shfl_xor_sync(0xffffffffu, v, 1);
                v += __shfl_xor_sync(0xffffffffu, v, 2);
                rs[i][hf] = v;
            }
        if (t4 == 0) {
#pragma unroll
            for (int i = 0; i < 2; i++)
#pragma unroll
                for (int hf = 0; hf < 2; hf++)
                    red_sum[warp_n * 64 + rloc0 + i * 16 + hf * 8] = rs[i][hf];
        }
#pragma unroll
        for (int i = 0; i < 2; i++)
#pragma unroll
            for (int hf = 0; hf < 2; hf++) {
                int r = rloc0 + i * 16 + hf * 8;
#pragma unroll
                for (int j = 0; j < 2; j++) {
                    float2 o;
                    o.x = rndf(S[i][j][hf * 2]);
                    o.y = rndf(S[i][j][hf * 2 + 1]);
                    *(float2*)(Pt + r * FL_STR + warp_n * 16 + j * 8 + t4 * 2) = o;
                }
            }
        __syncthreads();

        // ---- l update + rescale O ----
#pragma unroll
        for (int i = 0; i < 2; i++)
#pragma unroll
            for (int hf = 0; hf < 2; hf++) {
                int r = rloc0 + i * 16 + hf * 8;
                float tot = ((red_sum[r] + red_sum[64 + r]) +
                             (red_sum[128 + r] + red_sum[192 + r]));
                l_[i][hf] = l_[i][hf] * alpha[i][hf] + tot;
                float a = alpha[i][hf];
#pragma unroll
                for (int j = 0; j < 2; j++) {
                    Oa[i][j][hf * 2]     *= a;
                    Oa[i][j][hf * 2 + 1] *= a;
                }
            }

        // ---- O += P @ V ----
#pragma unroll
        for (int ks = 0; ks < 8; ks++) {
            int k0 = ks * 8;
            uint32_t a[2][4];
#pragma unroll
            for (int i = 0; i < 2; i++)
                ldsm4(a[i][0], a[i][1], a[i][2], a[i][3],
                      sb + FL_P + (uint32_t)((warp_m * 32 + i * 16 + a_lrow) * FL_STR + k0 + a_kofs) * 4);
            uint32_t b0, b1, b2, b3;
            ldsm4(b0, b1, b2, b3,
                  Vt + (uint32_t)((warp_n * 16 + b_nofs) * FL_STR + k0 + b_kofs) * 4);
#pragma unroll
            for (int i = 0; i < 2; i++) {
                mma16n8k8(Oa[i][0], a[i][0], a[i][1], a[i][2], a[i][3], b0, b1);
                mma16n8k8(Oa[i][1], a[i][0], a[i][1], a[i][2], a[i][3], b2, b3);
            }
        }
        __syncthreads();   // V fully consumed -> safe to refill V buffer

        if (kb + 1 < 9) {
            ldV(kb + 1);
            cp_commit();
        }
    }

    int h = wh & 15, w = wh >> 4;
    int bb = w / 9, wi = (w % 9) / 3, wj = w % 3;
#pragma unroll
    for (int i = 0; i < 2; i++)
#pragma unroll
        for (int hf = 0; hf < 2; hf++) {
            int s = qb * 64 + rloc0 + i * 16 + hf * 8;
            int r = s / 24, c = s - r * 24;
            int tok = bb * 5184 + (wi * 24 + r) * 72 + (wj * 24 + c);
            float inv = 1.f / l_[i][hf];
            float* orow = of + (size_t)tok * HS + h * HD;
#pragma unroll
            for (int j = 0; j < 2; j++) {
                float2 o;
                o.x = rndf(Oa[i][j][hf * 2]     * inv);
                o.y = rndf(Oa[i][j][hf * 2 + 1] * inv);
                *(float2*)(orow + warp_n * 16 + j * 8 + t4 * 2) = o;
            }
        }
}

// ---------------- host launch -----------------------------------------------
extern "C" void kernel_launch(void* const* d_in, const int* in_sizes, int n_in,
                              void* d_out, int out_size) {
    const float* hidden = (const float*)d_in[0];
    const float* ln1_g  = (const float*)d_in[1];
    const float* ln1_b  = (const float*)d_in[2];
    const float* wq = (const float*)d_in[3];
    const float* bq = (const float*)d_in[4];
    const float* wk = (const float*)d_in[5];
    const float* bk = (const float*)d_in[6];
    const float* wv = (const float*)d_in[7];
    const float* bv = (const float*)d_in[8];
    const float* wo = (const float*)d_in[9];
    const float* bo = (const float*)d_in[10];
    const float* ln2_g = (const float*)d_in[11];
    const float* ln2_b = (const float*)d_in[12];
    const float* w1 = (const float*)d_in[13];
    const float* b1 = (const float*)d_in[14];
    const float* w2 = (const float*)d_in[15];
    const float* b2 = (const float*)d_in[16];
    float* out = (float*)d_out;

    float *xn, *qw, *kw, *vwT, *of, *yn, *hm;
    float *wqkvT, *bqkv, *woT, *w1T, *w2T;
    cudaGetSymbolAddress((void**)&xn, g_xn);
    cudaGetSymbolAddress((void**)&qw, g_qw);
    cudaGetSymbolAddress((void**)&kw, g_kw);
    cudaGetSymbolAddress((void**)&vwT, g_vwT);
    cudaGetSymbolAddress((void**)&of, g_of);
    cudaGetSymbolAddress((void**)&yn, g_yn);
    cudaGetSymbolAddress((void**)&hm, g_hm);
    cudaGetSymbolAddress((void**)&wqkvT, g_wqkvT);
    cudaGetSymbolAddress((void**)&bqkv, g_bqkv);
    cudaGetSymbolAddress((void**)&woT, g_woT);
    cudaGetSymbolAddress((void**)&w1T, g_w1T);
    cudaGetSymbolAddress((void**)&w2T, g_w2T);

    cudaFuncSetAttribute(gemm_mma<1>, cudaFuncAttributeMaxDynamicSharedMemorySize, GEMM_SMEM);
    cudaFuncSetAttribute(gemm_mma<2>, cudaFuncAttributeMaxDynamicSharedMemorySize, GEMM_SMEM);
    cudaFuncSetAttribute(gemm_mma<3>, cudaFuncAttributeMaxDynamicSharedMemorySize, GEMM_SMEM);
    cudaFuncSetAttribute(gemm_mma<4>, cudaFuncAttributeMaxDynamicSharedMemorySize, GEMM_SMEM);
    cudaFuncSetAttribute(flash_attn, cudaFuncAttributeMaxDynamicSharedMemorySize, FL_SMEM);

    // 0) all transposes (+ tf32 round) + bias concat in one launch; LN1 separate
    transpose_all<<<12289, dim3(32, 8)>>>(wq, wk, wv, wo, w1, w2,
                                          wqkvT, woT, w1T, w2T,
                                          bq, bk, bv, bqkv);
    ln_kernel<<<N_TOK, 256>>>(hidden, ln1_g, ln1_b, xn);

    // 1) fused QKV projection + RoPE + window scatter
    gemm_mma<3><<<dim3(3 * HS / 128, N_TOK / 128), 256, GEMM_SMEM>>>(
        xn, wqkvT, bqkv, qw, nullptr, kw, vwT, HS, HS, 3 * HS);

    // 2) fused flash attention (3 CTAs/SM, early K prefetch)
    flash_attn<<<dim3(9, NWH), 256, FL_SMEM>>>(qw, kw, vwT, of);

    // 3) O projection + residual -> x (in d_out)
    dim3 gProj(HS / 128, N_TOK / 128);
    gemm_mma<2><<<gProj, 256, GEMM_SMEM>>>(of, woT, bo, out, hidden, nullptr, nullptr,
                                           HS, HS, HS);

    // 4) LN2
    ln_kernel<<<N_TOK, 256>>>(out, ln2_g, ln2_b, yn);

    // 5) MLP1 (GELU epilogue)
    gemm_mma<1><<<dim3(4096 / 128, N_TOK / 128), 256, GEMM_SMEM>>>(
        yn, w1T, b1, hm, nullptr, nullptr, nullptr, HS, HS, 4096);

    // 6) MLP2: single-launch split-K=2 (bx>=8 -> K-half 1) + fused reduce
    gemm_mma<4><<<dim3(16, N_TOK / 128), 256, GEMM_SMEM>>>(
        hm, w2T, nullptr, xn, nullptr, of, nullptr, 4096, 2048, HS);
    splitk_reduce<<<N_TOK * HS / 1024, 256>>>(xn, of, b2, out);
}

// round 16
// speedup vs baseline: 1.0064x; 1.0040x over previous
#include <cuda_runtime.h>
#include <cstdint>
#include <math.h>

#define N_TOK 10368          // 2*72*72
#define HS    1024
#define NWH   288            // 18 windows * 16 heads
#define S_WIN 576            // 24*24
#define HD    64

// ---------------- scratch (static device arrays; no runtime allocation) ----
__device__ float g_xn[N_TOK * HS];              // LN1 out; later split-K partial 0
__device__ float g_qw[NWH * S_WIN * HD];
__device__ float g_kw[NWH * S_WIN * HD];
__device__ float g_vwT[NWH * HD * S_WIN];       // [wh][d][s]
__device__ float g_of[N_TOK * HS];              // attn out; later split-K partial 1
__device__ float g_yn[N_TOK * HS];
__device__ float g_hm[(size_t)N_TOK * 4096];
// transposed (k-major) tf32-rounded weights
__device__ float g_wqkvT[3 * HS * HS];          // [3072][1024]
__device__ float g_bqkv[3 * HS];
__device__ float g_woT[HS * HS];
__device__ float g_w1T[HS * 4096];
__device__ float g_w2T[HS * 4096];

// ============================ helpers =======================================
__device__ __forceinline__ uint32_t smem_u32(const void* p) {
    uint32_t a;
    asm("{ .reg .u64 t; cvta.to.shared.u64 t, %1; cvt.u32.u64 %0, t; }"
        : "=r"(a) : "l"(p));
    return a;
}

__device__ __forceinline__ float rndf(float x) {   // round fp32 -> tf32-representable
    uint32_t r;
    asm("cvt.rna.tf32.f32 %0, %1;" : "=r"(r) : "f"(x));
    return __uint_as_float(r);
}

__device__ __forceinline__ void cp16(uint32_t dst, const void* src) {
    asm volatile("cp.async.cg.shared.global [%0], [%1], 16;"
                 :: "r"(dst), "l"(src) : "memory");
}
__device__ __forceinline__ void cp_commit() {
    asm volatile("cp.async.commit_group;" ::: "memory");
}
template <int N>
__device__ __forceinline__ void cp_wait() {
    asm volatile("cp.async.wait_group %0;" :: "n"(N) : "memory");
}

__device__ __forceinline__ void mma16n8k8(float* c, uint32_t a0, uint32_t a1,
                                          uint32_t a2, uint32_t a3,
                                          uint32_t b0, uint32_t b1) {
    asm volatile(
        "mma.sync.aligned.m16n8k8.row.col.f32.tf32.tf32.f32 "
        "{%0,%1,%2,%3}, {%4,%5,%6,%7}, {%8,%9}, {%0,%1,%2,%3};"
        : "+f"(c[0]), "+f"(c[1]), "+f"(c[2]), "+f"(c[3])
        : "r"(a0), "r"(a1), "r"(a2), "r"(a3), "r"(b0), "r"(b1));
}

__device__ __forceinline__ void ldsm4(uint32_t& r0, uint32_t& r1, uint32_t& r2,
                                      uint32_t& r3, uint32_t addr) {
    asm volatile("ldmatrix.sync.aligned.m8n8.x4.shared.b16 {%0,%1,%2,%3}, [%4];"
                 : "=r"(r0), "=r"(r1), "=r"(r2), "=r"(r3) : "r"(addr));
}

// ============================ tf32 mma.sync GEMM ============================
// C[M,N] = A[M,K] @ Bt[n][k]^T + bias.  A and Bt k-major, pre-rounded tf32.
// EPI 1: exact GELU(+round)  2: +residual  3: QKV+RoPE scatter
// EPI 4: split-K partial store (grid.x doubled; bx>>3 selects K-half;
//        half 0 -> C, half 1 -> O2; no bias)
// K = row stride; Klen = K extent this block reduces over.
// 3-stage cp.async pipeline, ONE barrier per chunk (2 groups in flight).
#define STR36 36
#define TILE_BYTES (128 * STR36 * 4)      // 18432
#define BUF_BYTES (2 * TILE_BYTES)        // 36864 per stage (A+B)
#define GEMM_SMEM (3 * BUF_BYTES)         // 110592

template <int EPI>
__global__ void __launch_bounds__(256, 2) gemm_mma(
    const float* __restrict__ A, const float* __restrict__ Bt,
    const float* __restrict__ bias, float* __restrict__ C,
    const float* __restrict__ R, float* __restrict__ O2,
    float* __restrict__ O3, int K, int Klen, int N) {
    extern __shared__ char smem[];
    const int tid = threadIdx.x;
    const int wid = tid >> 5, lane = tid & 31;
    const int g = lane >> 2, t4 = lane & 3;
    const int warp_m = wid & 3, warp_n = wid >> 2;

    uint32_t sb = smem_u32(smem);
    int bxn = blockIdx.x, koff = 0;
    if (EPI == 4) { bxn = blockIdx.x & 7; koff = (blockIdx.x >> 3) * Klen; }
    const float* Ag = A + (size_t)blockIdx.y * 128 * K + koff;
    const float* Bg = Bt + (size_t)bxn * 128 * K + koff;

    float acc[2][8][4];
#pragma unroll
    for (int i = 0; i < 2; i++)
#pragma unroll
        for (int j = 0; j < 8; j++)
#pragma unroll
            for (int t = 0; t < 4; t++) acc[i][j][t] = 0.f;

    auto prefetch = [&](int ck, int buf) {
        uint32_t as = sb + buf * BUF_BYTES;
        uint32_t bs = as + TILE_BYTES;
#pragma unroll
        for (int t = 0; t < 4; t++) {
            int slot = tid + t * 256;
            int r = slot >> 3, kq = slot & 7;
            uint32_t so = (uint32_t)(r * STR36 + kq * 4) * 4;
            cp16(as + so, Ag + (size_t)r * K + ck * 32 + kq * 4);
            cp16(bs + so, Bg + (size_t)r * K + ck * 32 + kq * 4);
        }
    };

    const int a_lrow = lane & 15;
    const int a_kofs = ((lane >> 4) << 2);
    const int b_nofs = (lane & 7) + ((lane >> 4) << 3);
    const int b_kofs = (((lane >> 3) & 1) << 2);

    auto compute = [&](int buf) {
        uint32_t as = sb + buf * BUF_BYTES;
        uint32_t bs = as + TILE_BYTES;
#pragma unroll
        for (int ks = 0; ks < 4; ks++) {
            int k0 = ks * 8;
            uint32_t a[2][4];
#pragma unroll
            for (int i = 0; i < 2; i++) {
                uint32_t addr = as +
                    (uint32_t)((warp_m * 32 + i * 16 + a_lrow) * STR36 + k0 + a_kofs) * 4;
                ldsm4(a[i][0], a[i][1], a[i][2], a[i][3], addr);
            }
#pragma unroll
            for (int j2 = 0; j2 < 4; j2++) {
                uint32_t b0, b1, b2, b3;
                uint32_t baddr = bs +
                    (uint32_t)((warp_n * 64 + j2 * 16 + b_nofs) * STR36 + k0 + b_kofs) * 4;
                ldsm4(b0, b1, b2, b3, baddr);
#pragma unroll
                for (int i = 0; i < 2; i++) {
                    mma16n8k8(acc[i][2 * j2 + 0], a[i][0], a[i][1], a[i][2], a[i][3], b0, b1);
                    mma16n8k8(acc[i][2 * j2 + 1], a[i][0], a[i][1], a[i][2], a[i][3], b2, b3);
                }
            }
        }
    };

    // one-barrier-per-chunk 3-stage pipeline (2 groups in flight):
    //   cp_wait(ck landed) ; sync ; prefetch(ck+2 -> buffer (ck-1)%3) ; compute(ck)
    const int nch = Klen / 32;
    prefetch(0, 0);
    cp_commit();
    prefetch(1, 1);
    cp_commit();
    int s2 = 2;
    for (int ck = 0; ck < nch; ck++) {
        if (ck + 1 < nch) cp_wait<1>(); else cp_wait<0>();
        __syncthreads();
        if (ck + 2 < nch) {
            prefetch(ck + 2, s2);
            cp_commit();
            if (++s2 == 3) s2 = 0;
        }
        compute(ck % 3);
    }

    // ---------------- epilogue ----------------
    if (EPI <= 2) {
        const int colb = blockIdx.x * 128 + warp_n * 64;
        const size_t row0 = (size_t)blockIdx.y * 128 + warp_m * 32 + g;
#pragma unroll
        for (int i = 0; i < 2; i++) {
            size_t r0 = row0 + i * 16;
#pragma unroll
            for (int j = 0; j < 8; j++) {
                int c = colb + j * 8 + t4 * 2;
                float b0 = bias[c], b1 = bias[c + 1];
#pragma unroll
                for (int half = 0; half < 2; half++) {
                    size_t r = r0 + half * 8;
                    float v0 = acc[i][j][half * 2 + 0] + b0;
                    float v1 = acc[i][j][half * 2 + 1] + b1;
                    if (EPI == 1) {
                        v0 = rndf(0.5f * v0 * (1.0f + erff(v0 * 0.70710678118654752f)));
                        v1 = rndf(0.5f * v1 * (1.0f + erff(v1 * 0.70710678118654752f)));
                    }
                    if (EPI == 2) {
                        const float2 rr = *(const float2*)(R + r * N + c);
                        v0 += rr.x; v1 += rr.y;
                    }
                    float2 o; o.x = v0; o.y = v1;
                    *(float2*)(C + r * N + c) = o;
                }
            }
        }
    } else if (EPI == 4) {
        // ---- split-K partial store (raw acc, no bias) ----
        float* Cs = (blockIdx.x < 8) ? C : O2;
        const int colb = bxn * 128 + warp_n * 64;
        const size_t row0 = (size_t)blockIdx.y * 128 + warp_m * 32 + g;
#pragma unroll
        for (int i = 0; i < 2; i++) {
            size_t r0 = row0 + i * 16;
#pragma unroll
            for (int j = 0; j < 8; j++) {
                int c = colb + j * 8 + t4 * 2;
#pragma unroll
                for (int half = 0; half < 2; half++) {
                    size_t r = r0 + half * 8;
                    float2 o;
                    o.x = acc[i][j][half * 2 + 0];
                    o.y = acc[i][j][half * 2 + 1];
                    *(float2*)(Cs + r * N + c) = o;
                }
            }
        }
    } else {
        // ---- fused QKV + RoPE + window scatter (EPI == 3) ----
        const int bx = blockIdx.x;
        const int mat = bx >> 3;                      // 0=q 1=k 2=v
        const int hh = ((bx & 7) << 1) + warp_n;      // head 0..15
        int wh_[2][2], s_[2][2], ry_[2][2], cx_[2][2];
#pragma unroll
        for (int i = 0; i < 2; i++)
#pragma unroll
            for (int half = 0; half < 2; half++) {
                int rr = blockIdx.y * 128 + warp_m * 32 + g + i * 16 + half * 8;
                int b_ = rr / 5184, rem = rr - b_ * 5184;
                int y = rem / 72, x = rem - y * 72;
                int wi = y / 24, ry = y - wi * 24;
                int wj = x / 24, cx = x - wj * 24;
                wh_[i][half] = (b_ * 9 + wi * 3 + wj) * 16 + hh;
                s_[i][half] = ry * 24 + cx;
                ry_[i][half] = ry;
                cx_[i][half] = cx;
            }
#pragma unroll
        for (int j = 0; j < 8; j++) {
            const int d = j * 8 + t4 * 2;             // 0..62 even
            const int p = j * 4 + t4;                 // pair index 0..31
            const int jx = p & 15;
            const int xy = p >> 4;
            const float freq = exp2f(-0.830482023722f * (float)jx);
            const int cglob = bx * 128 + warp_n * 64 + d;
            const float b0 = bias[cglob], b1 = bias[cglob + 1];
#pragma unroll
            for (int i = 0; i < 2; i++)
#pragma unroll
                for (int half = 0; half < 2; half++) {
                    float v0 = acc[i][j][half * 2 + 0] + b0;
                    float v1 = acc[i][j][half * 2 + 1] + b1;
                    if (mat == 2) {
                        size_t vb = ((size_t)wh_[i][half] * HD + d) * S_WIN + s_[i][half];
                        O3[vb] = rndf(v0);
                        O3[vb + S_WIN] = rndf(v1);
                    } else {
                        float pos = (xy ? (float)ry_[i][half] : (float)cx_[i][half])
                                    * (1.0f / 3.0f);
                        float sn, cs;
                        __sincosf(pos * freq, &sn, &cs);
                        float o0 = v0 * cs - v1 * sn;
                        float o1 = v1 * cs + v0 * sn;
                        if (mat == 0) { o0 *= 0.125f; o1 *= 0.125f; }
                        float* dstp = (mat == 0) ? C : O2;
                        size_t off = ((size_t)wh_[i][half] * S_WIN + s_[i][half]) * HD + d;
                        float2 o; o.x = rndf(o0); o.y = rndf(o1);
                        *(float2*)(dstp + off) = o;
                    }
                }
        }
    }
}

// ---------------- split-K reduce: out += p0 + p1 + bias ----------------------
__global__ void splitk_reduce(const float* __restrict__ p0, const float* __restrict__ p1,
                              const float* __restrict__ b, float* __restrict__ out) {
    size_t i = ((size_t)blockIdx.x * 256 + threadIdx.x) * 4;
    int c = (int)(i & (HS - 1));
    float4 a0 = *(const float4*)(p0 + i);
    float4 a1 = *(const float4*)(p1 + i);
    float4 oo = *(const float4*)(out + i);
    oo.x += a0.x + a1.x + b[c];
    oo.y += a0.y + a1.y + b[c + 1];
    oo.z += a0.z + a1.z + b[c + 2];
    oo.w += a0.w + a1.w + b[c + 3];
    *(float4*)(out + i) = oo;
}

// ---------------- ALL weight transposes + bias concat in ONE launch ---------
__global__ void transpose_all(const float* __restrict__ wq, const float* __restrict__ wk,
                              const float* __restrict__ wv, const float* __restrict__ wo,
                              const float* __restrict__ w1, const float* __restrict__ w2,
                              float* __restrict__ wqkvT, float* __restrict__ woT,
                              float* __restrict__ w1T, float* __restrict__ w2T,
                              const float* __restrict__ bq, const float* __restrict__ bk,
                              const float* __restrict__ bv, float* __restrict__ bqkv) {
    __shared__ float t[32][33];
    int id = blockIdx.x;
    if (id == 12288) {
        int tid = threadIdx.y * 32 + threadIdx.x;
#pragma unroll
        for (int it = 0; it < 12; it++) {
            int i = tid + it * 256;
            if (i < HS) bqkv[i] = bq[i];
            else if (i < 2 * HS) bqkv[i] = bk[i - HS];
            else bqkv[i] = bv[i - 2 * HS];
        }
        return;
    }
    const float* in;
    float* out;
    int Rr, Cc, bx, by;
    if (id < 4096) {
        int seg = id >> 10, l = id & 1023;
        in = (seg == 0) ? wq : (seg == 1) ? wk : (seg == 2) ? wv : wo;
        out = (seg == 3) ? woT : wqkvT + (size_t)seg * HS * HS;
        Rr = HS; Cc = HS;
        bx = (l & 31) * 32; by = (l >> 5) * 32;
    } else if (id < 8192) {
        int l = id - 4096;
        in = w1; out = w1T; Rr = HS; Cc = 4096;
        bx = (l & 127) * 32; by = (l >> 7) * 32;
    } else {
        int l = id - 8192;
        in = w2; out = w2T; Rr = 4096; Cc = HS;
        bx = (l & 31) * 32; by = (l >> 5) * 32;
    }
    int x = bx + threadIdx.x;
    int y = by + threadIdx.y;
#pragma unroll
    for (int i = 0; i < 32; i += 8)
        t[threadIdx.y + i][threadIdx.x] = in[(size_t)(y + i) * Cc + x];
    __syncthreads();
#pragma unroll
    for (int i = 0; i < 32; i += 8)
        out[(size_t)(bx + threadIdx.y + i) * Rr + by + threadIdx.x] =
            rndf(t[threadIdx.x][threadIdx.y + i]);
}

// ---------------- LayerNorm (tf32-rounded output) ----------------------------
__global__ void ln_kernel(const float* __restrict__ x, const float* __restrict__ g,
                          const float* __restrict__ b, float* __restrict__ out) {
    int row = blockIdx.x;
    int tid = threadIdx.x;
    const float* xr = x + (size_t)row * HS;
    float v[4];
    float s = 0.f, sq = 0.f;
#pragma unroll
    for (int i = 0; i < 4; i++) {
        v[i] = xr[tid + i * 256];
        s += v[i];
        sq += v[i] * v[i];
    }
#pragma unroll
    for (int o = 16; o; o >>= 1) {
        s  += __shfl_xor_sync(0xffffffffu, s, o);
        sq += __shfl_xor_sync(0xffffffffu, sq, o);
    }
    __shared__ float rs[8], rq[8];
    __shared__ float mean_s, rstd_s;
    if ((tid & 31) == 0) { rs[tid >> 5] = s; rq[tid >> 5] = sq; }
    __syncthreads();
    if (tid == 0) {
        float a = 0.f, c = 0.f;
        for (int k = 0; k < 8; k++) { a += rs[k]; c += rq[k]; }
        float m = a * (1.f / HS);
        float var = c * (1.f / HS) - m * m;
        mean_s = m;
        rstd_s = rsqrtf(var + 1e-6f);
    }
    __syncthreads();
    float m = mean_s, r = rstd_s;
    float* orow = out + (size_t)row * HS;
#pragma unroll
    for (int i = 0; i < 4; i++) {
        int c = tid + i * 256;
        orow[c] = rndf((v[i] - m) * r * g[c] + b[c]);
    }
}

// ================= fused flash attention per (wh, 64-q-row block) ===========
// grid (9, 288), 256 threads (8 warps: 2m x 4n, warp tile 32x16).
// 3 CTAs/SM.  Split cp.async wait groups: prologue commits {Q,K0} then {V0};
// loop top cp_wait<1> waits only K (S needs just K, V stays in flight);
// V is waited at the pre-PV barrier -> V load covered by S+softmax phase.
#define FL_STR 68
#define FL_TILE_B (64 * FL_STR * 4)       // 17408
#define FL_Q 0
#define FL_K FL_TILE_B
#define FL_V (2 * FL_TILE_B)
#define FL_P (3 * FL_TILE_B)
#define FL_RED (4 * FL_TILE_B)
#define FL_SMEM (4 * FL_TILE_B + 2048)    // 71680 -> 3 CTAs/SM (215 KB)

__global__ void __launch_bounds__(256, 3) flash_attn(
    const float* __restrict__ qw, const float* __restrict__ kw,
    const float* __restrict__ vwT, float* __restrict__ of) {
    extern __shared__ char smem[];
    uint32_t sb = smem_u32(smem);
    const int tid = threadIdx.x;
    const int wid = tid >> 5, lane = tid & 31;
    const int g = lane >> 2, t4 = lane & 3;
    const int warp_m = wid >> 2, warp_n = wid & 3;
    const int wh = blockIdx.y, qb = blockIdx.x;

    const float* Qg = qw + ((size_t)wh * S_WIN + qb * 64) * HD;
    const float* Kg = kw + (size_t)wh * S_WIN * HD;
    const float* Vg = vwT + (size_t)wh * HD * S_WIN;

    auto ldK = [&](int kb) {
#pragma unroll
        for (int t = 0; t < 4; t++) {
            int slot = tid + t * 256;
            int r = slot >> 4, kq = slot & 15;
            cp16(sb + FL_K + (uint32_t)(r * FL_STR + kq * 4) * 4,
                 Kg + (size_t)(kb * 64 + r) * HD + kq * 4);
        }
    };
    auto ldV = [&](int kb) {
#pragma unroll
        for (int t = 0; t < 4; t++) {
            int slot = tid + t * 256;
            int d = slot >> 4, sq = slot & 15;
            cp16(sb + FL_V + (uint32_t)(d * FL_STR + sq * 4) * 4,
                 Vg + (size_t)d * S_WIN + kb * 64 + sq * 4);
        }
    };

    // prologue: group 1 = {Q, K0}; group 2 = {V0}
#pragma unroll
    for (int t = 0; t < 4; t++) {
        int slot = tid + t * 256;
        int r = slot >> 4, kq = slot & 15;
        cp16(sb + FL_Q + (uint32_t)(r * FL_STR + kq * 4) * 4,
             Qg + (size_t)r * HD + kq * 4);
    }
    ldK(0);
    cp_commit();
    ldV(0);
    cp_commit();

    float m_[2][2], l_[2][2], Oa[2][2][4];
#pragma unroll
    for (int i = 0; i < 2; i++)
#pragma unroll
        for (int hf = 0; hf < 2; hf++) { m_[i][hf] = -1e30f; l_[i][hf] = 0.f; }
#pragma unroll
    for (int i = 0; i < 2; i++)
#pragma unroll
        for (int j = 0; j < 2; j++)
#pragma unroll
            for (int t = 0; t < 4; t++) Oa[i][j][t] = 0.f;

    float* red_max = (float*)(smem + FL_RED);   // [4][64]
    float* red_sum = red_max + 256;             // [4][64]
    float* Pt = (float*)(smem + FL_P);
    const uint32_t Kt = sb + FL_K;
    const uint32_t Vt = sb + FL_V;

    const int a_lrow = lane & 15;
    const int a_kofs = ((lane >> 4) << 2);
    const int b_nofs = (lane & 7) + ((lane >> 4) << 3);
    const int b_kofs = (((lane >> 3) & 1) << 2);

    const int rloc0 = warp_m * 32 + g;

    for (int kb = 0; kb < 9; kb++) {
        cp_wait<1>();      // K (older group) ready; V may still be in flight
        __syncthreads();

        // ---- S = Q @ K^T ----
        float S[2][2][4];
#pragma unroll
        for (int i = 0; i < 2; i++)
#pragma unroll
            for (int j = 0; j < 2; j++)
#pragma unroll
                for (int t = 0; t < 4; t++) S[i][j][t] = 0.f;
#pragma unroll
        for (int ks = 0; ks < 8; ks++) {
            int k0 = ks * 8;
            uint32_t a[2][4];
#pragma unroll
            for (int i = 0; i < 2; i++)
                ldsm4(a[i][0], a[i][1], a[i][2], a[i][3],
                      sb + FL_Q + (uint32_t)((warp_m * 32 + i * 16 + a_lrow) * FL_STR + k0 + a_kofs) * 4);
            uint32_t b0, b1, b2, b3;
            ldsm4(b0, b1, b2, b3,
                  Kt + (uint32_t)((warp_n * 16 + b_nofs) * FL_STR + k0 + b_kofs) * 4);
#pragma unroll
            for (int i = 0; i < 2; i++) {
                mma16n8k8(S[i][0], a[i][0], a[i][1], a[i][2], a[i][3], b0, b1);
                mma16n8k8(S[i][1], a[i][0], a[i][1], a[i][2], a[i][3], b2, b3);
            }
        }

        // ---- row max ----
        float mx[2][2];
#pragma unroll
        for (int i = 0; i < 2; i++)
#pragma unroll
            for (int hf = 0; hf < 2; hf++) {
                float v = fmaxf(fmaxf(S[i][0][hf * 2], S[i][0][hf * 2 + 1]),
                                fmaxf(S[i][1][hf * 2], S[i][1][hf * 2 + 1]));
                v = fmaxf(v, __shfl_xor_sync(0xffffffffu, v, 1));
                v = fmaxf(v, __shfl_xor_sync(0xffffffffu, v, 2));
                mx[i][hf] = v;
            }
        if (t4 == 0) {
#pragma unroll
            for (int i = 0; i < 2; i++)
#pragma unroll
                for (int hf = 0; hf < 2; hf++)
                    red_max[warp_n * 64 + rloc0 + i * 16 + hf * 8] = mx[i][hf];
        }
        __syncthreads();   // all K reads done -> safe to refill K buffer

        // issue next K load NOW: covered by softmax + P write + PV below
        if (kb + 1 < 9) {
            ldK(kb + 1);
            cp_commit();
        }

        float alpha[2][2];
#pragma unroll
        for (int i = 0; i < 2; i++)
#pragma unroll
            for (int hf = 0; hf < 2; hf++) {
                int r = rloc0 + i * 16 + hf * 8;
                float tm = fmaxf(fmaxf(red_max[r], red_max[64 + r]),
                                 fmaxf(red_max[128 + r], red_max[192 + r]));
                float mn = fmaxf(m_[i][hf], tm);
                alpha[i][hf] = __expf(m_[i][hf] - mn);
                m_[i][hf] = mn;
            }

        float rs[2][2];
#pragma unroll
        for (int i = 0; i < 2; i++)
#pragma unroll
            for (int hf = 0; hf < 2; hf++) {
                float m = m_[i][hf];
                float e0 = __expf(S[i][0][hf * 2]     - m);
                float e1 = __expf(S[i][0][hf * 2 + 1] - m);
                float e2 = __expf(S[i][1][hf * 2]     - m);
                float e3 = __expf(S[i][1][hf * 2 + 1] - m);
                S[i][0][hf * 2] = e0; S[i][0][hf * 2 + 1] = e1;
                S[i][1][hf * 2] = e2; S[i][1][hf * 2 + 1] = e3;
                float v = (e0 + e1) + (e2 + e3);
                v += __shfl_xor_sync(0xffffffffu, v, 1);
                v += __shfl_xor_sync(0xffffffffu, v, 2);
                rs[i][hf] = v;
            }
        if (t4 == 0) {
#pragma unroll
            for (int i = 0; i < 2; i++)
#pragma unroll
                for (int hf = 0; hf < 2; hf++)
                    red_sum[warp_n * 64 + rloc0 + i * 16 + hf * 8] = rs[i][hf];
        }
#pragma unroll
        for (int i = 0; i < 2; i++)
#pragma unroll
            for (int hf = 0; hf < 2; hf++) {
                int r = rloc0 + i * 16 + hf * 8;
#pragma unroll
                for (int j = 0; j < 2; j++) {
                    float2 o;
                    o.x = rndf(S[i][j][hf * 2]);
                    o.y = rndf(S[i][j][hf * 2 + 1]);
                    *(float2*)(Pt + r * FL_STR + warp_n * 16 + j * 8 + t4 * 2) = o;
                }
            }
        // wait V (older outstanding group); K(kb+1) group may stay in flight
        if (kb + 1 < 9) cp_wait<1>(); else cp_wait<0>();
        __syncthreads();   // P + V visible to all threads

        // ---- l update + rescale O ----
#pragma unroll
        for (int i = 0; i < 2; i++)
#pragma unroll
            for (int hf = 0; hf < 2; hf++) {
                int r = rloc0 + i * 16 + hf * 8;
                float tot = ((red_sum[r] + red_sum[64 + r]) +
                             (red_sum[128 + r] + red_sum[192 + r]));
                l_[i][hf] = l_[i][hf] * alpha[i][hf] + tot;
                float a = alpha[i][hf];
#pragma unroll
                for (int j = 0; j < 2; j++) {
                    Oa[i][j][hf * 2]     *= a;
                    Oa[i][j][hf * 2 + 1] *= a;
                }
            }

        // ---- O += P @ V ----
#pragma unroll
        for (int ks = 0; ks < 8; ks++) {
            int k0 = ks * 8;
            uint32_t a[2][4];
#pragma unroll
            for (int i = 0; i < 2; i++)
                ldsm4(a[i][0], a[i][1], a[i][2], a[i][3],
                      sb + FL_P + (uint32_t)((warp_m * 32 + i * 16 + a_lrow) * FL_STR + k0 + a_kofs) * 4);
            uint32_t b0, b1, b2, b3;
            ldsm4(b0, b1, b2, b3,
                  Vt + (uint32_t)((warp_n * 16 + b_nofs) * FL_STR + k0 + b_kofs) * 4);
#pragma unroll
            for (int i = 0; i < 2; i++) {
                mma16n8k8(Oa[i][0], a[i][0], a[i][1], a[i][2], a[i][3], b0, b1);
                mma16n8k8(Oa[i][1], a[i][0], a[i][1], a[i][2], a[i][3], b2, b3);
            }
        }
        __syncthreads();   // V fully consumed -> safe to refill V buffer

        if (kb + 1 < 9) {
            ldV(kb + 1);
            cp_commit();
        }
    }

    int h = wh & 15, w = wh >> 4;
    int bb = w / 9, wi = (w % 9) / 3, wj = w % 3;
#pragma unroll
    for (int i = 0; i < 2; i++)
#pragma unroll
        for (int hf = 0; hf < 2; hf++) {
            int s = qb * 64 + rloc0 + i * 16 + hf * 8;
            int r = s / 24, c = s - r * 24;
            int tok = bb * 5184 + (wi * 24 + r) * 72 + (wj * 24 + c);
            float inv = 1.f / l_[i][hf];
            float* orow = of + (size_t)tok * HS + h * HD;
#pragma unroll
            for (int j = 0; j < 2; j++) {
                float2 o;
                o.x = rndf(Oa[i][j][hf * 2]     * inv);
                o.y = rndf(Oa[i][j][hf * 2 + 1] * inv);
                *(float2*)(orow + warp_n * 16 + j * 8 + t4 * 2) = o;
            }
        }
}

// ---------------- host launch -----------------------------------------------
extern "C" void kernel_launch(void* const* d_in, const int* in_sizes, int n_in,
                              void* d_out, int out_size) {
    const float* hidden = (const float*)d_in[0];
    const float* ln1_g  = (const float*)d_in[1];
    const float* ln1_b  = (const float*)d_in[2];
    const float* wq = (const float*)d_in[3];
    const float* bq = (const float*)d_in[4];
    const float* wk = (const float*)d_in[5];
    const float* bk = (const float*)d_in[6];
    const float* wv = (const float*)d_in[7];
    const float* bv = (const float*)d_in[8];
    const float* wo = (const float*)d_in[9];
    const float* bo = (const float*)d_in[10];
    const float* ln2_g = (const float*)d_in[11];
    const float* ln2_b = (const float*)d_in[12];
    const float* w1 = (const float*)d_in[13];
    const float* b1 = (const float*)d_in[14];
    const float* w2 = (const float*)d_in[15];
    const float* b2 = (const float*)d_in[16];
    float* out = (float*)d_out;

    float *xn, *qw, *kw, *vwT, *of, *yn, *hm;
    float *wqkvT, *bqkv, *woT, *w1T, *w2T;
    cudaGetSymbolAddress((void**)&xn, g_xn);
    cudaGetSymbolAddress((void**)&qw, g_qw);
    cudaGetSymbolAddress((void**)&kw, g_kw);
    cudaGetSymbolAddress((void**)&vwT, g_vwT);
    cudaGetSymbolAddress((void**)&of, g_of);
    cudaGetSymbolAddress((void**)&yn, g_yn);
    cudaGetSymbolAddress((void**)&hm, g_hm);
    cudaGetSymbolAddress((void**)&wqkvT, g_wqkvT);
    cudaGetSymbolAddress((void**)&bqkv, g_bqkv);
    cudaGetSymbolAddress((void**)&woT, g_woT);
    cudaGetSymbolAddress((void**)&w1T, g_w1T);
    cudaGetSymbolAddress((void**)&w2T, g_w2T);

    cudaFuncSetAttribute(gemm_mma<1>, cudaFuncAttributeMaxDynamicSharedMemorySize, GEMM_SMEM);
    cudaFuncSetAttribute(gemm_mma<2>, cudaFuncAttributeMaxDynamicSharedMemorySize, GEMM_SMEM);
    cudaFuncSetAttribute(gemm_mma<3>, cudaFuncAttributeMaxDynamicSharedMemorySize, GEMM_SMEM);
    cudaFuncSetAttribute(gemm_mma<4>, cudaFuncAttributeMaxDynamicSharedMemorySize, GEMM_SMEM);
    cudaFuncSetAttribute(flash_attn, cudaFuncAttributeMaxDynamicSharedMemorySize, FL_SMEM);

    // 0) all transposes (+ tf32 round) + bias concat in one launch; LN1 separate
    transpose_all<<<12289, dim3(32, 8)>>>(wq, wk, wv, wo, w1, w2,
                                          wqkvT, woT, w1T, w2T,
                                          bq, bk, bv, bqkv);
    ln_kernel<<<N_TOK, 256>>>(hidden, ln1_g, ln1_b, xn);

    // 1) fused QKV projection + RoPE + window scatter
    gemm_mma<3><<<dim3(3 * HS / 128, N_TOK / 128), 256, GEMM_SMEM>>>(
        xn, wqkvT, bqkv, qw, nullptr, kw, vwT, HS, HS, 3 * HS);

    // 2) fused flash attention (3 CTAs/SM, split K/V wait groups)
    flash_attn<<<dim3(9, NWH), 256, FL_SMEM>>>(qw, kw, vwT, of);

    // 3) O projection + residual -> x (in d_out)
    dim3 gProj(HS / 128, N_TOK / 128);
    gemm_mma<2><<<gProj, 256, GEMM_SMEM>>>(of, woT, bo, out, hidden, nullptr, nullptr,
                                           HS, HS, HS);

    // 4) LN2
    ln_kernel<<<N_TOK, 256>>>(out, ln2_g, ln2_b, yn);

    // 5) MLP1 (GELU epilogue)
    gemm_mma<1><<<dim3(4096 / 128, N_TOK / 128), 256, GEMM_SMEM>>>(
        yn, w1T, b1, hm, nullptr, nullptr, nullptr, HS, HS, 4096);

    // 6) MLP2: single-launch split-K=2 (bx>=8 -> K-half 1) + fused reduce
    gemm_mma<4><<<dim3(16, N_TOK / 128), 256, GEMM_SMEM>>>(
        hm, w2T, nullptr, xn, nullptr, of, nullptr, 4096, 2048, HS);
    splitk_reduce<<<N_TOK * HS / 1024, 256>>>(xn, of, b2, out);
}

// round 17
// speedup vs baseline: 1.0066x; 1.0003x over previous
#include <cuda_runtime.h>
#include <cstdint>
#include <math.h>

#define N_TOK 10368          // 2*72*72
#define HS    1024
#define NWH   288            // 18 windows * 16 heads
#define S_WIN 576            // 24*24
#define HD    64

// ---------------- scratch (static device arrays; no runtime allocation) ----
__device__ float g_xn[N_TOK * HS];              // LN1 out; later split-K partial 0
__device__ float g_qw[NWH * S_WIN * HD];
__device__ float g_kw[NWH * S_WIN * HD];
__device__ float g_vwT[NWH * HD * S_WIN];       // [wh][d][s]
__device__ float g_of[N_TOK * HS];              // attn out; later split-K partial 1
__device__ float g_yn[N_TOK * HS];
__device__ float g_hm[(size_t)N_TOK * 4096];
// transposed (k-major) tf32-rounded weights
__device__ float g_wqkvT[3 * HS * HS];          // [3072][1024]
__device__ float g_bqkv[3 * HS];
__device__ float g_woT[HS * HS];
__device__ float g_w1T[HS * 4096];
__device__ float g_w2T[HS * 4096];

// ============================ helpers =======================================
__device__ __forceinline__ uint32_t smem_u32(const void* p) {
    uint32_t a;
    asm("{ .reg .u64 t; cvta.to.shared.u64 t, %1; cvt.u32.u64 %0, t; }"
        : "=r"(a) : "l"(p));
    return a;
}

__device__ __forceinline__ float rndf(float x) {   // round fp32 -> tf32-representable
    uint32_t r;
    asm("cvt.rna.tf32.f32 %0, %1;" : "=r"(r) : "f"(x));
    return __uint_as_float(r);
}

__device__ __forceinline__ void cp16(uint32_t dst, const void* src) {
    asm volatile("cp.async.cg.shared.global [%0], [%1], 16;"
                 :: "r"(dst), "l"(src) : "memory");
}
__device__ __forceinline__ void cp_commit() {
    asm volatile("cp.async.commit_group;" ::: "memory");
}
template <int N>
__device__ __forceinline__ void cp_wait() {
    asm volatile("cp.async.wait_group %0;" :: "n"(N) : "memory");
}

__device__ __forceinline__ void mma16n8k8(float* c, uint32_t a0, uint32_t a1,
                                          uint32_t a2, uint32_t a3,
                                          uint32_t b0, uint32_t b1) {
    asm volatile(
        "mma.sync.aligned.m16n8k8.row.col.f32.tf32.tf32.f32 "
        "{%0,%1,%2,%3}, {%4,%5,%6,%7}, {%8,%9}, {%0,%1,%2,%3};"
        : "+f"(c[0]), "+f"(c[1]), "+f"(c[2]), "+f"(c[3])
        : "r"(a0), "r"(a1), "r"(a2), "r"(a3), "r"(b0), "r"(b1));
}

__device__ __forceinline__ void ldsm4(uint32_t& r0, uint32_t& r1, uint32_t& r2,
                                      uint32_t& r3, uint32_t addr) {
    asm volatile("ldmatrix.sync.aligned.m8n8.x4.shared.b16 {%0,%1,%2,%3}, [%4];"
                 : "=r"(r0), "=r"(r1), "=r"(r2), "=r"(r3) : "r"(addr));
}

// ============================ tf32 mma.sync GEMM ============================
// C[M,N] = A[M,K] @ Bt[n][k]^T + bias.  A and Bt k-major, pre-rounded tf32.
// EPI 1: exact GELU(+round)  2: +residual  3: QKV+RoPE scatter
// EPI 4: split-K partial store (grid.x doubled; bx>>3 selects K-half;
//        half 0 -> C, half 1 -> O2; no bias)
// K = row stride; Klen = K extent this block reduces over.
// 3-stage cp.async pipeline, ONE barrier per chunk (2 groups in flight).
#define STR36 36
#define TILE_BYTES (128 * STR36 * 4)      // 18432
#define BUF_BYTES (2 * TILE_BYTES)        // 36864 per stage (A+B)
#define GEMM_SMEM (3 * BUF_BYTES)         // 110592

template <int EPI>
__global__ void __launch_bounds__(256, 2) gemm_mma(
    const float* __restrict__ A, const float* __restrict__ Bt,
    const float* __restrict__ bias, float* __restrict__ C,
    const float* __restrict__ R, float* __restrict__ O2,
    float* __restrict__ O3, int K, int Klen, int N) {
    extern __shared__ char smem[];
    const int tid = threadIdx.x;
    const int wid = tid >> 5, lane = tid & 31;
    const int g = lane >> 2, t4 = lane & 3;
    const int warp_m = wid & 3, warp_n = wid >> 2;

    uint32_t sb = smem_u32(smem);
    int bxn = blockIdx.x, koff = 0;
    if (EPI == 4) { bxn = blockIdx.x & 7; koff = (blockIdx.x >> 3) * Klen; }
    const float* Ag = A + (size_t)blockIdx.y * 128 * K + koff;
    const float* Bg = Bt + (size_t)bxn * 128 * K + koff;

    float acc[2][8][4];
#pragma unroll
    for (int i = 0; i < 2; i++)
#pragma unroll
        for (int j = 0; j < 8; j++)
#pragma unroll
            for (int t = 0; t < 4; t++) acc[i][j][t] = 0.f;

    auto prefetch = [&](int ck, int buf) {
        uint32_t as = sb + buf * BUF_BYTES;
        uint32_t bs = as + TILE_BYTES;
#pragma unroll
        for (int t = 0; t < 4; t++) {
            int slot = tid + t * 256;
            int r = slot >> 3, kq = slot & 7;
            uint32_t so = (uint32_t)(r * STR36 + kq * 4) * 4;
            cp16(as + so, Ag + (size_t)r * K + ck * 32 + kq * 4);
            cp16(bs + so, Bg + (size_t)r * K + ck * 32 + kq * 4);
        }
    };

    const int a_lrow = lane & 15;
    const int a_kofs = ((lane >> 4) << 2);
    const int b_nofs = (lane & 7) + ((lane >> 4) << 3);
    const int b_kofs = (((lane >> 3) & 1) << 2);

    auto compute = [&](int buf) {
        uint32_t as = sb + buf * BUF_BYTES;
        uint32_t bs = as + TILE_BYTES;
#pragma unroll
        for (int ks = 0; ks < 4; ks++) {
            int k0 = ks * 8;
            uint32_t a[2][4];
#pragma unroll
            for (int i = 0; i < 2; i++) {
                uint32_t addr = as +
                    (uint32_t)((warp_m * 32 + i * 16 + a_lrow) * STR36 + k0 + a_kofs) * 4;
                ldsm4(a[i][0], a[i][1], a[i][2], a[i][3], addr);
            }
#pragma unroll
            for (int j2 = 0; j2 < 4; j2++) {
                uint32_t b0, b1, b2, b3;
                uint32_t baddr = bs +
                    (uint32_t)((warp_n * 64 + j2 * 16 + b_nofs) * STR36 + k0 + b_kofs) * 4;
                ldsm4(b0, b1, b2, b3, baddr);
#pragma unroll
                for (int i = 0; i < 2; i++) {
                    mma16n8k8(acc[i][2 * j2 + 0], a[i][0], a[i][1], a[i][2], a[i][3], b0, b1);
                    mma16n8k8(acc[i][2 * j2 + 1], a[i][0], a[i][1], a[i][2], a[i][3], b2, b3);
                }
            }
        }
    };

    // one-barrier-per-chunk 3-stage pipeline (2 groups in flight):
    //   cp_wait(ck landed) ; sync ; prefetch(ck+2 -> buffer (ck-1)%3) ; compute(ck)
    const int nch = Klen / 32;
    prefetch(0, 0);
    cp_commit();
    prefetch(1, 1);
    cp_commit();
    int s2 = 2;
    for (int ck = 0; ck < nch; ck++) {
        if (ck + 1 < nch) cp_wait<1>(); else cp_wait<0>();
        __syncthreads();
        if (ck + 2 < nch) {
            prefetch(ck + 2, s2);
            cp_commit();
            if (++s2 == 3) s2 = 0;
        }
        compute(ck % 3);
    }

    // ---------------- epilogue ----------------
    if (EPI <= 2) {
        const int colb = blockIdx.x * 128 + warp_n * 64;
        const size_t row0 = (size_t)blockIdx.y * 128 + warp_m * 32 + g;
#pragma unroll
        for (int i = 0; i < 2; i++) {
            size_t r0 = row0 + i * 16;
#pragma unroll
            for (int j = 0; j < 8; j++) {
                int c = colb + j * 8 + t4 * 2;
                float b0 = bias[c], b1 = bias[c + 1];
#pragma unroll
                for (int half = 0; half < 2; half++) {
                    size_t r = r0 + half * 8;
                    float v0 = acc[i][j][half * 2 + 0] + b0;
                    float v1 = acc[i][j][half * 2 + 1] + b1;
                    if (EPI == 1) {
                        v0 = rndf(0.5f * v0 * (1.0f + erff(v0 * 0.70710678118654752f)));
                        v1 = rndf(0.5f * v1 * (1.0f + erff(v1 * 0.70710678118654752f)));
                    }
                    if (EPI == 2) {
                        const float2 rr = *(const float2*)(R + r * N + c);
                        v0 += rr.x; v1 += rr.y;
                    }
                    float2 o; o.x = v0; o.y = v1;
                    *(float2*)(C + r * N + c) = o;
                }
            }
        }
    } else if (EPI == 4) {
        // ---- split-K partial store (raw acc, no bias) ----
        float* Cs = (blockIdx.x < 8) ? C : O2;
        const int colb = bxn * 128 + warp_n * 64;
        const size_t row0 = (size_t)blockIdx.y * 128 + warp_m * 32 + g;
#pragma unroll
        for (int i = 0; i < 2; i++) {
            size_t r0 = row0 + i * 16;
#pragma unroll
            for (int j = 0; j < 8; j++) {
                int c = colb + j * 8 + t4 * 2;
#pragma unroll
                for (int half = 0; half < 2; half++) {
                    size_t r = r0 + half * 8;
                    float2 o;
                    o.x = acc[i][j][half * 2 + 0];
                    o.y = acc[i][j][half * 2 + 1];
                    *(float2*)(Cs + r * N + c) = o;
                }
            }
        }
    } else {
        // ---- fused QKV + RoPE + window scatter (EPI == 3) ----
        const int bx = blockIdx.x;
        const int mat = bx >> 3;                      // 0=q 1=k 2=v
        const int hh = ((bx & 7) << 1) + warp_n;      // head 0..15
        int wh_[2][2], s_[2][2], ry_[2][2], cx_[2][2];
#pragma unroll
        for (int i = 0; i < 2; i++)
#pragma unroll
            for (int half = 0; half < 2; half++) {
                int rr = blockIdx.y * 128 + warp_m * 32 + g + i * 16 + half * 8;
                int b_ = rr / 5184, rem = rr - b_ * 5184;
                int y = rem / 72, x = rem - y * 72;
                int wi = y / 24, ry = y - wi * 24;
                int wj = x / 24, cx = x - wj * 24;
                wh_[i][half] = (b_ * 9 + wi * 3 + wj) * 16 + hh;
                s_[i][half] = ry * 24 + cx;
                ry_[i][half] = ry;
                cx_[i][half] = cx;
            }
#pragma unroll
        for (int j = 0; j < 8; j++) {
            const int d = j * 8 + t4 * 2;             // 0..62 even
            const int p = j * 4 + t4;                 // pair index 0..31
            const int jx = p & 15;
            const int xy = p >> 4;
            const float freq = exp2f(-0.830482023722f * (float)jx);
            const int cglob = bx * 128 + warp_n * 64 + d;
            const float b0 = bias[cglob], b1 = bias[cglob + 1];
#pragma unroll
            for (int i = 0; i < 2; i++)
#pragma unroll
                for (int half = 0; half < 2; half++) {
                    float v0 = acc[i][j][half * 2 + 0] + b0;
                    float v1 = acc[i][j][half * 2 + 1] + b1;
                    if (mat == 2) {
                        size_t vb = ((size_t)wh_[i][half] * HD + d) * S_WIN + s_[i][half];
                        O3[vb] = rndf(v0);
                        O3[vb + S_WIN] = rndf(v1);
                    } else {
                        float pos = (xy ? (float)ry_[i][half] : (float)cx_[i][half])
                                    * (1.0f / 3.0f);
                        float sn, cs;
                        __sincosf(pos * freq, &sn, &cs);
                        float o0 = v0 * cs - v1 * sn;
                        float o1 = v1 * cs + v0 * sn;
                        if (mat == 0) { o0 *= 0.125f; o1 *= 0.125f; }
                        float* dstp = (mat == 0) ? C : O2;
                        size_t off = ((size_t)wh_[i][half] * S_WIN + s_[i][half]) * HD + d;
                        float2 o; o.x = rndf(o0); o.y = rndf(o1);
                        *(float2*)(dstp + off) = o;
                    }
                }
        }
    }
}

// ---------------- split-K reduce: out += p0 + p1 + bias ----------------------
__global__ void splitk_reduce(const float* __restrict__ p0, const float* __restrict__ p1,
                              const float* __restrict__ b, float* __restrict__ out) {
    size_t i = ((size_t)blockIdx.x * 256 + threadIdx.x) * 4;
    int c = (int)(i & (HS - 1));
    float4 a0 = *(const float4*)(p0 + i);
    float4 a1 = *(const float4*)(p1 + i);
    float4 oo = *(const float4*)(out + i);
    oo.x += a0.x + a1.x + b[c];
    oo.y += a0.y + a1.y + b[c + 1];
    oo.z += a0.z + a1.z + b[c + 2];
    oo.w += a0.w + a1.w + b[c + 3];
    *(float4*)(out + i) = oo;
}

// ---------------- ALL weight transposes + bias concat in ONE launch ---------
__global__ void transpose_all(const float* __restrict__ wq, const float* __restrict__ wk,
                              const float* __restrict__ wv, const float* __restrict__ wo,
                              const float* __restrict__ w1, const float* __restrict__ w2,
                              float* __restrict__ wqkvT, float* __restrict__ woT,
                              float* __restrict__ w1T, float* __restrict__ w2T,
                              const float* __restrict__ bq, const float* __restrict__ bk,
                              const float* __restrict__ bv, float* __restrict__ bqkv) {
    __shared__ float t[32][33];
    int id = blockIdx.x;
    if (id == 12288) {
        int tid = threadIdx.y * 32 + threadIdx.x;
#pragma unroll
        for (int it = 0; it < 12; it++) {
            int i = tid + it * 256;
            if (i < HS) bqkv[i] = bq[i];
            else if (i < 2 * HS) bqkv[i] = bk[i - HS];
            else bqkv[i] = bv[i - 2 * HS];
        }
        return;
    }
    const float* in;
    float* out;
    int Rr, Cc, bx, by;
    if (id < 4096) {
        int seg = id >> 10, l = id & 1023;
        in = (seg == 0) ? wq : (seg == 1) ? wk : (seg == 2) ? wv : wo;
        out = (seg == 3) ? woT : wqkvT + (size_t)seg * HS * HS;
        Rr = HS; Cc = HS;
        bx = (l & 31) * 32; by = (l >> 5) * 32;
    } else if (id < 8192) {
        int l = id - 4096;
        in = w1; out = w1T; Rr = HS; Cc = 4096;
        bx = (l & 127) * 32; by = (l >> 7) * 32;
    } else {
        int l = id - 8192;
        in = w2; out = w2T; Rr = 4096; Cc = HS;
        bx = (l & 31) * 32; by = (l >> 5) * 32;
    }
    int x = bx + threadIdx.x;
    int y = by + threadIdx.y;
#pragma unroll
    for (int i = 0; i < 32; i += 8)
        t[threadIdx.y + i][threadIdx.x] = in[(size_t)(y + i) * Cc + x];
    __syncthreads();
#pragma unroll
    for (int i = 0; i < 32; i += 8)
        out[(size_t)(bx + threadIdx.y + i) * Rr + by + threadIdx.x] =
            rndf(t[threadIdx.x][threadIdx.y + i]);
}

// ---------------- LayerNorm (tf32-rounded output) ----------------------------
__global__ void ln_kernel(const float* __restrict__ x, const float* __restrict__ g,
                          const float* __restrict__ b, float* __restrict__ out) {
    int row = blockIdx.x;
    int tid = threadIdx.x;
    const float* xr = x + (size_t)row * HS;
    float v[4];
    float s = 0.f, sq = 0.f;
#pragma unroll
    for (int i = 0; i < 4; i++) {
        v[i] = xr[tid + i * 256];
        s += v[i];
        sq += v[i] * v[i];
    }
#pragma unroll
    for (int o = 16; o; o >>= 1) {
        s  += __shfl_xor_sync(0xffffffffu, s, o);
        sq += __shfl_xor_sync(0xffffffffu, sq, o);
    }
    __shared__ float rs[8], rq[8];
    __shared__ float mean_s, rstd_s;
    if ((tid & 31) == 0) { rs[tid >> 5] = s; rq[tid >> 5] = sq; }
    __syncthreads();
    if (tid == 0) {
        float a = 0.f, c = 0.f;
        for (int k = 0; k < 8; k++) { a += rs[k]; c += rq[k]; }
        float m = a * (1.f / HS);
        float var = c * (1.f / HS) - m * m;
        mean_s = m;
        rstd_s = rsqrtf(var + 1e-6f);
    }
    __syncthreads();
    float m = mean_s, r = rstd_s;
    float* orow = out + (size_t)row * HS;
#pragma unroll
    for (int i = 0; i < 4; i++) {
        int c = tid + i * 256;
        orow[c] = rndf((v[i] - m) * r * g[c] + b[c]);
    }
}

// ================= fused flash attention per (wh, 64-q-row block) ===========
// grid (9, 288), 256 threads (8 warps: 2m x 4n, warp tile 32x16).
// 3 CTAs/SM.  Split cp.async wait groups (K waited at top, V at pre-PV
// barrier).  Oa rescale hoisted to right after alpha (before P write) so the
// post-V-wait critical path holds only l_ update + PV MMAs.
#define FL_STR 68
#define FL_TILE_B (64 * FL_STR * 4)       // 17408
#define FL_Q 0
#define FL_K FL_TILE_B
#define FL_V (2 * FL_TILE_B)
#define FL_P (3 * FL_TILE_B)
#define FL_RED (4 * FL_TILE_B)
#define FL_SMEM (4 * FL_TILE_B + 2048)    // 71680 -> 3 CTAs/SM (215 KB)

__global__ void __launch_bounds__(256, 3) flash_attn(
    const float* __restrict__ qw, const float* __restrict__ kw,
    const float* __restrict__ vwT, float* __restrict__ of) {
    extern __shared__ char smem[];
    uint32_t sb = smem_u32(smem);
    const int tid = threadIdx.x;
    const int wid = tid >> 5, lane = tid & 31;
    const int g = lane >> 2, t4 = lane & 3;
    const int warp_m = wid >> 2, warp_n = wid & 3;
    const int wh = blockIdx.y, qb = blockIdx.x;

    const float* Qg = qw + ((size_t)wh * S_WIN + qb * 64) * HD;
    const float* Kg = kw + (size_t)wh * S_WIN * HD;
    const float* Vg = vwT + (size_t)wh * HD * S_WIN;

    auto ldK = [&](int kb) {
#pragma unroll
        for (int t = 0; t < 4; t++) {
            int slot = tid + t * 256;
            int r = slot >> 4, kq = slot & 15;
            cp16(sb + FL_K + (uint32_t)(r * FL_STR + kq * 4) * 4,
                 Kg + (size_t)(kb * 64 + r) * HD + kq * 4);
        }
    };
    auto ldV = [&](int kb) {
#pragma unroll
        for (int t = 0; t < 4; t++) {
            int slot = tid + t * 256;
            int d = slot >> 4, sq = slot & 15;
            cp16(sb + FL_V + (uint32_t)(d * FL_STR + sq * 4) * 4,
                 Vg + (size_t)d * S_WIN + kb * 64 + sq * 4);
        }
    };

    // prologue: group 1 = {Q, K0}; group 2 = {V0}
#pragma unroll
    for (int t = 0; t < 4; t++) {
        int slot = tid + t * 256;
        int r = slot >> 4, kq = slot & 15;
        cp16(sb + FL_Q + (uint32_t)(r * FL_STR + kq * 4) * 4,
             Qg + (size_t)r * HD + kq * 4);
    }
    ldK(0);
    cp_commit();
    ldV(0);
    cp_commit();

    float m_[2][2], l_[2][2], Oa[2][2][4];
#pragma unroll
    for (int i = 0; i < 2; i++)
#pragma unroll
        for (int hf = 0; hf < 2; hf++) { m_[i][hf] = -1e30f; l_[i][hf] = 0.f; }
#pragma unroll
    for (int i = 0; i < 2; i++)
#pragma unroll
        for (int j = 0; j < 2; j++)
#pragma unroll
            for (int t = 0; t < 4; t++) Oa[i][j][t] = 0.f;

    float* red_max = (float*)(smem + FL_RED);   // [4][64]
    float* red_sum = red_max + 256;             // [4][64]
    float* Pt = (float*)(smem + FL_P);
    const uint32_t Kt = sb + FL_K;
    const uint32_t Vt = sb + FL_V;

    const int a_lrow = lane & 15;
    const int a_kofs = ((lane >> 4) << 2);
    const int b_nofs = (lane & 7) + ((lane >> 4) << 3);
    const int b_kofs = (((lane >> 3) & 1) << 2);

    const int rloc0 = warp_m * 32 + g;

    for (int kb = 0; kb < 9; kb++) {
        cp_wait<1>();      // K (older group) ready; V may still be in flight
        __syncthreads();

        // ---- S = Q @ K^T ----
        float S[2][2][4];
#pragma unroll
        for (int i = 0; i < 2; i++)
#pragma unroll
            for (int j = 0; j < 2; j++)
#pragma unroll
                for (int t = 0; t < 4; t++) S[i][j][t] = 0.f;
#pragma unroll
        for (int ks = 0; ks < 8; ks++) {
            int k0 = ks * 8;
            uint32_t a[2][4];
#pragma unroll
            for (int i = 0; i < 2; i++)
                ldsm4(a[i][0], a[i][1], a[i][2], a[i][3],
                      sb + FL_Q + (uint32_t)((warp_m * 32 + i * 16 + a_lrow) * FL_STR + k0 + a_kofs) * 4);
            uint32_t b0, b1, b2, b3;
            ldsm4(b0, b1, b2, b3,
                  Kt + (uint32_t)((warp_n * 16 + b_nofs) * FL_STR + k0 + b_kofs) * 4);
#pragma unroll
            for (int i = 0; i < 2; i++) {
                mma16n8k8(S[i][0], a[i][0], a[i][1], a[i][2], a[i][3], b0, b1);
                mma16n8k8(S[i][1], a[i][0], a[i][1], a[i][2], a[i][3], b2, b3);
            }
        }

        // ---- row max ----
        float mx[2][2];
#pragma unroll
        for (int i = 0; i < 2; i++)
#pragma unroll
            for (int hf = 0; hf < 2; hf++) {
                float v = fmaxf(fmaxf(S[i][0][hf * 2], S[i][0][hf * 2 + 1]),
                                fmaxf(S[i][1][hf * 2], S[i][1][hf * 2 + 1]));
                v = fmaxf(v, __shfl_xor_sync(0xffffffffu, v, 1));
                v = fmaxf(v, __shfl_xor_sync(0xffffffffu, v, 2));
                mx[i][hf] = v;
            }
        if (t4 == 0) {
#pragma unroll
            for (int i = 0; i < 2; i++)
#pragma unroll
                for (int hf = 0; hf < 2; hf++)
                    red_max[warp_n * 64 + rloc0 + i * 16 + hf * 8] = mx[i][hf];
        }
        __syncthreads();   // all K reads done -> safe to refill K buffer

        // issue next K load NOW: covered by softmax + P write + PV below
        if (kb + 1 < 9) {
            ldK(kb + 1);
            cp_commit();
        }

        float alpha[2][2];
#pragma unroll
        for (int i = 0; i < 2; i++)
#pragma unroll
            for (int hf = 0; hf < 2; hf++) {
                int r = rloc0 + i * 16 + hf * 8;
                float tm = fmaxf(fmaxf(red_max[r], red_max[64 + r]),
                                 fmaxf(red_max[128 + r], red_max[192 + r]));
                float mn = fmaxf(m_[i][hf], tm);
                alpha[i][hf] = __expf(m_[i][hf] - mn);
                m_[i][hf] = mn;
            }

        // Oa rescale hoisted here: depends only on alpha; runs in the shadow
        // of the softmax/P-write phase instead of after the V wait.
#pragma unroll
        for (int i = 0; i < 2; i++)
#pragma unroll
            for (int hf = 0; hf < 2; hf++) {
                float a = alpha[i][hf];
#pragma unroll
                for (int j = 0; j < 2; j++) {
                    Oa[i][j][hf * 2]     *= a;
                    Oa[i][j][hf * 2 + 1] *= a;
                }
            }

        float rs[2][2];
#pragma unroll
        for (int i = 0; i < 2; i++)
#pragma unroll
            for (int hf = 0; hf < 2; hf++) {
                float m = m_[i][hf];
                float e0 = __expf(S[i][0][hf * 2]     - m);
                float e1 = __expf(S[i][0][hf * 2 + 1] - m);
                float e2 = __expf(S[i][1][hf * 2]     - m);
                float e3 = __expf(S[i][1][hf * 2 + 1] - m);
                S[i][0][hf * 2] = e0; S[i][0][hf * 2 + 1] = e1;
                S[i][1][hf * 2] = e2; S[i][1][hf * 2 + 1] = e3;
                float v = (e0 + e1) + (e2 + e3);
                v += __shfl_xor_sync(0xffffffffu, v, 1);
                v += __shfl_xor_sync(0xffffffffu, v, 2);
                rs[i][hf] = v;
            }
        if (t4 == 0) {
#pragma unroll
            for (int i = 0; i < 2; i++)
#pragma unroll
                for (int hf = 0; hf < 2; hf++)
                    red_sum[warp_n * 64 + rloc0 + i * 16 + hf * 8] = rs[i][hf];
        }
#pragma unroll
        for (int i = 0; i < 2; i++)
#pragma unroll
            for (int hf = 0; hf < 2; hf++) {
                int r = rloc0 + i * 16 + hf * 8;
#pragma unroll
                for (int j = 0; j < 2; j++) {
                    float2 o;
                    o.x = rndf(S[i][j][hf * 2]);
                    o.y = rndf(S[i][j][hf * 2 + 1]);
                    *(float2*)(Pt + r * FL_STR + warp_n * 16 + j * 8 + t4 * 2) = o;
                }
            }
        // wait V (older outstanding group); K(kb+1) group may stay in flight
        if (kb + 1 < 9) cp_wait<1>(); else cp_wait<0>();
        __syncthreads();   // P + V visible to all threads

        // ---- l update (Oa already rescaled above) ----
#pragma unroll
        for (int i = 0; i < 2; i++)
#pragma unroll
            for (int hf = 0; hf < 2; hf++) {
                int r = rloc0 + i * 16 + hf * 8;
                float tot = ((red_sum[r] + red_sum[64 + r]) +
                             (red_sum[128 + r] + red_sum[192 + r]));
                l_[i][hf] = l_[i][hf] * alpha[i][hf] + tot;
            }

        // ---- O += P @ V ----
#pragma unroll
        for (int ks = 0; ks < 8; ks++) {
            int k0 = ks * 8;
            uint32_t a[2][4];
#pragma unroll
            for (int i = 0; i < 2; i++)
                ldsm4(a[i][0], a[i][1], a[i][2], a[i][3],
                      sb + FL_P + (uint32_t)((warp_m * 32 + i * 16 + a_lrow) * FL_STR + k0 + a_kofs) * 4);
            uint32_t b0, b1, b2, b3;
            ldsm4(b0, b1, b2, b3,
                  Vt + (uint32_t)((warp_n * 16 + b_nofs) * FL_STR + k0 + b_kofs) * 4);
#pragma unroll
            for (int i = 0; i < 2; i++) {
                mma16n8k8(Oa[i][0], a[i][0], a[i][1], a[i][2], a[i][3], b0, b1);
                mma16n8k8(Oa[i][1], a[i][0], a[i][1], a[i][2], a[i][3], b2, b3);
            }
        }
        __syncthreads();   // V fully consumed -> safe to refill V buffer

        if (kb + 1 < 9) {
            ldV(kb + 1);
            cp_commit();
        }
    }

    int h = wh & 15, w = wh >> 4;
    int bb = w / 9, wi = (w % 9) / 3, wj = w % 3;
#pragma unroll
    for (int i = 0; i < 2; i++)
#pragma unroll
        for (int hf = 0; hf < 2; hf++) {
            int s = qb * 64 + rloc0 + i * 16 + hf * 8;
            int r = s / 24, c = s - r * 24;
            int tok = bb * 5184 + (wi * 24 + r) * 72 + (wj * 24 + c);
            float inv = 1.f / l_[i][hf];
            float* orow = of + (size_t)tok * HS + h * HD;
#pragma unroll
            for (int j = 0; j < 2; j++) {
                float2 o;
                o.x = rndf(Oa[i][j][hf * 2]     * inv);
                o.y = rndf(Oa[i][j][hf * 2 + 1] * inv);
                *(float2*)(orow + warp_n * 16 + j * 8 + t4 * 2) = o;
            }
        }
}

// ---------------- host launch -----------------------------------------------
extern "C" void kernel_launch(void* const* d_in, const int* in_sizes, int n_in,
                              void* d_out, int out_size) {
    const float* hidden = (const float*)d_in[0];
    const float* ln1_g  = (const float*)d_in[1];
    const float* ln1_b  = (const float*)d_in[2];
    const float* wq = (const float*)d_in[3];
    const float* bq = (const float*)d_in[4];
    const float* wk = (const float*)d_in[5];
    const float* bk = (const float*)d_in[6];
    const float* wv = (const float*)d_in[7];
    const float* bv = (const float*)d_in[8];
    const float* wo = (const float*)d_in[9];
    const float* bo = (const float*)d_in[10];
    const float* ln2_g = (const float*)d_in[11];
    const float* ln2_b = (const float*)d_in[12];
    const float* w1 = (const float*)d_in[13];
    const float* b1 = (const float*)d_in[14];
    const float* w2 = (const float*)d_in[15];
    const float* b2 = (const float*)d_in[16];
    float* out = (float*)d_out;

    float *xn, *qw, *kw, *vwT, *of, *yn, *hm;
    float *wqkvT, *bqkv, *woT, *w1T, *w2T;
    cudaGetSymbolAddress((void**)&xn, g_xn);
    cudaGetSymbolAddress((void**)&qw, g_qw);
    cudaGetSymbolAddress((void**)&kw, g_kw);
    cudaGetSymbolAddress((void**)&vwT, g_vwT);
    cudaGetSymbolAddress((void**)&of, g_of);
    cudaGetSymbolAddress((void**)&yn, g_yn);
    cudaGetSymbolAddress((void**)&hm, g_hm);
    cudaGetSymbolAddress((void**)&wqkvT, g_wqkvT);
    cudaGetSymbolAddress((void**)&bqkv, g_bqkv);
    cudaGetSymbolAddress((void**)&woT, g_woT);
    cudaGetSymbolAddress((void**)&w1T, g_w1T);
    cudaGetSymbolAddress((void**)&w2T, g_w2T);

    cudaFuncSetAttribute(gemm_mma<1>, cudaFuncAttributeMaxDynamicSharedMemorySize, GEMM_SMEM);
    cudaFuncSetAttribute(gemm_mma<2>, cudaFuncAttributeMaxDynamicSharedMemorySize, GEMM_SMEM);
    cudaFuncSetAttribute(gemm_mma<3>, cudaFuncAttributeMaxDynamicSharedMemorySize, GEMM_SMEM);
    cudaFuncSetAttribute(gemm_mma<4>, cudaFuncAttributeMaxDynamicSharedMemorySize, GEMM_SMEM);
    cudaFuncSetAttribute(flash_attn, cudaFuncAttributeMaxDynamicSharedMemorySize, FL_SMEM);

    // 0) all transposes (+ tf32 round) + bias concat in one launch; LN1 separate
    transpose_all<<<12289, dim3(32, 8)>>>(wq, wk, wv, wo, w1, w2,
                                          wqkvT, woT, w1T, w2T,
                                          bq, bk, bv, bqkv);
    ln_kernel<<<N_TOK, 256>>>(hidden, ln1_g, ln1_b, xn);

    // 1) fused QKV projection + RoPE + window scatter
    gemm_mma<3><<<dim3(3 * HS / 128, N_TOK / 128), 256, GEMM_SMEM>>>(
        xn, wqkvT, bqkv, qw, nullptr, kw, vwT, HS, HS, 3 * HS);

    // 2) fused flash attention (3 CTAs/SM, split K/V wait groups)
    flash_attn<<<dim3(9, NWH), 256, FL_SMEM>>>(qw, kw, vwT, of);

    // 3) O projection + residual -> x (in d_out)
    dim3 gProj(HS / 128, N_TOK / 128);
    gemm_mma<2><<<gProj, 256, GEMM_SMEM>>>(of, woT, bo, out, hidden, nullptr, nullptr,
                                           HS, HS, HS);

    // 4) LN2
    ln_kernel<<<N_TOK, 256>>>(out, ln2_g, ln2_b, yn);

    // 5) MLP1 (GELU epilogue)
    gemm_mma<1><<<dim3(4096 / 128, N_TOK / 128), 256, GEMM_SMEM>>>(
        yn, w1T, b1, hm, nullptr, nullptr, nullptr, HS, HS, 4096);

    // 6) MLP2: single-launch split-K=2 (bx>=8 -> K-half 1) + fused reduce
    gemm_mma<4><<<dim3(16, N_TOK / 128), 256, GEMM_SMEM>>>(
        hm, w2T, nullptr, xn, nullptr, of, nullptr, 4096, 2048, HS);
    splitk_reduce<<<N_TOK * HS / 1024, 256>>>(xn, of, b2, out);
}